// round 1
// baseline (speedup 1.0000x reference)
#include <cuda_runtime.h>
#include <cstddef>

// Problem dims (fixed by the reference)
#define D_MODEL 1024
#define SEQ     2048
#define BATCH   2
#define NH      16
#define DK      64
#define DFF     4096
#define MTOT    (BATCH * SEQ)   // 4096 rows

// ---------------------------------------------------------------------------
// Scratch (no allocation allowed -> __device__ globals)
// ---------------------------------------------------------------------------
__device__ float g_q   [MTOT * D_MODEL];
__device__ float g_k   [MTOT * D_MODEL];
__device__ float g_v   [MTOT * D_MODEL];
__device__ float g_attn[MTOT * D_MODEL];
__device__ float g_x1  [MTOT * D_MODEL];
__device__ float g_tmp [MTOT * D_MODEL];
__device__ float g_h   [MTOT * DFF];

// ---------------------------------------------------------------------------
// GEMM: C = A[MxK] @ W[KxN] + bias, optional ReLU or +res epilogue.
// 128x128 block tile, BK=8, 256 threads, 8x8 per-thread register tile.
// EPI: 0 = bias, 1 = bias+relu, 2 = bias+res
// All dims are multiples of the tile sizes here (no bounds checks).
// ---------------------------------------------------------------------------
#define BM 128
#define BN 128
#define BK 8
#define TM 8
#define TN 8

template <int EPI>
__global__ __launch_bounds__(256)
void gemm_kernel(const float* __restrict__ A, const float* __restrict__ W,
                 const float* __restrict__ bias, const float* __restrict__ res,
                 float* __restrict__ C, int M, int N, int K)
{
    __shared__ float As[BK][BM];
    __shared__ float Bs[BK][BN];

    const int tid = threadIdx.x;
    const int bm  = blockIdx.y * BM;
    const int bn  = blockIdx.x * BN;
    const int tx  = tid & 15;     // 0..15  (column group)
    const int ty  = tid >> 4;     // 0..15  (row group)

    float acc[TM][TN];
#pragma unroll
    for (int i = 0; i < TM; i++)
#pragma unroll
        for (int j = 0; j < TN; j++) acc[i][j] = 0.f;

    // A-tile loader: each thread loads float4 from A row (bm+arow), cols acol..acol+3
    const int arow = tid >> 1;
    const int acol = (tid & 1) * 4;
    // B-tile loader: each thread loads float4 from W row brow, cols bn+bcol..+3
    const int brow = tid >> 5;
    const int bcol = (tid & 31) * 4;

    const float* Aptr = A + (size_t)(bm + arow) * K + acol;
    const float* Wptr = W + (size_t)brow * N + bn + bcol;

    for (int k0 = 0; k0 < K; k0 += BK) {
        float4 av = *(const float4*)(Aptr + k0);
        As[acol + 0][arow] = av.x;
        As[acol + 1][arow] = av.y;
        As[acol + 2][arow] = av.z;
        As[acol + 3][arow] = av.w;
        float4 bv = *(const float4*)(Wptr + (size_t)k0 * N);
        *(float4*)&Bs[brow][bcol] = bv;
        __syncthreads();

#pragma unroll
        for (int k = 0; k < BK; k++) {
            float ra[TM], rb[TN];
            *(float4*)&ra[0] = *(const float4*)&As[k][ty * TM];
            *(float4*)&ra[4] = *(const float4*)&As[k][ty * TM + 4];
            *(float4*)&rb[0] = *(const float4*)&Bs[k][tx * TN];
            *(float4*)&rb[4] = *(const float4*)&Bs[k][tx * TN + 4];
#pragma unroll
            for (int i = 0; i < TM; i++)
#pragma unroll
                for (int j = 0; j < TN; j++)
                    acc[i][j] += ra[i] * rb[j];
        }
        __syncthreads();
    }

    // epilogue
    const int nbase = bn + tx * TN;
    float bb[TN];
#pragma unroll
    for (int j = 0; j < TN; j++) bb[j] = bias[nbase + j];

#pragma unroll
    for (int i = 0; i < TM; i++) {
        const int m = bm + ty * TM + i;
        float* crow = C + (size_t)m * N + nbase;
        const float* rrow = (EPI == 2) ? (res + (size_t)m * N + nbase) : nullptr;
#pragma unroll
        for (int j = 0; j < TN; j += 4) {
            float4 cv;
            cv.x = acc[i][j + 0] + bb[j + 0];
            cv.y = acc[i][j + 1] + bb[j + 1];
            cv.z = acc[i][j + 2] + bb[j + 2];
            cv.w = acc[i][j + 3] + bb[j + 3];
            if (EPI == 1) {
                cv.x = fmaxf(cv.x, 0.f); cv.y = fmaxf(cv.y, 0.f);
                cv.z = fmaxf(cv.z, 0.f); cv.w = fmaxf(cv.w, 0.f);
            }
            if (EPI == 2) {
                float4 rv = *(const float4*)(rrow + j);
                cv.x += rv.x; cv.y += rv.y; cv.z += rv.z; cv.w += rv.w;
            }
            *(float4*)(crow + j) = cv;
        }
    }
}

// ---------------------------------------------------------------------------
// Flash attention, fp32. Grid: (SEQ/QT, BATCH*NH). 256 threads.
// Q/K/V layout: [B, S, H*DK] row-major (head h = cols h*64..h*64+63).
// QT=64 queries per block, KT=32 keys per inner tile, online softmax.
// ---------------------------------------------------------------------------
#define QT 64
#define KT 32
#define KPAD 68   // 68 % 32 == 4 -> conflict-free rows, 16B-aligned rows

__global__ __launch_bounds__(256)
void attn_kernel(const float* __restrict__ Q, const float* __restrict__ K,
                 const float* __restrict__ V, float* __restrict__ O)
{
    __shared__ float qs[QT][KPAD];
    __shared__ float ks[KT][KPAD];
    __shared__ float vs[KT][KPAD];
    __shared__ float sc[QT][KT];
    __shared__ float m_s[QT], l_s[QT], f_s[QT];

    const int tid = threadIdx.x;
    const int bh  = blockIdx.y;
    const int b   = bh >> 4;
    const int h   = bh & 15;
    const int q0  = blockIdx.x * QT;
    const float scale = 0.125f;  // 1/sqrt(64)

    const size_t base = (size_t)b * SEQ * D_MODEL + (size_t)h * DK;

    // load Q tile (scaled)
#pragma unroll
    for (int e = 0; e < (QT * DK) / 256; e++) {
        int idx = tid + 256 * e;
        int qq = idx >> 6, d = idx & 63;
        qs[qq][d] = Q[base + (size_t)(q0 + qq) * D_MODEL + d] * scale;
    }
    if (tid < QT) { m_s[tid] = -1e30f; l_s[tid] = 0.f; }

    const int qq = tid >> 6;   // 0..3 : query group
    const int dd = tid & 63;   // output dim
    float o[16];
#pragma unroll
    for (int i = 0; i < 16; i++) o[i] = 0.f;
    __syncthreads();

    for (int k0 = 0; k0 < SEQ; k0 += KT) {
        // load K,V tiles (coalesced)
#pragma unroll
        for (int e = 0; e < (KT * DK) / 256; e++) {
            int idx = tid + 256 * e;
            int kk = idx >> 6, d = idx & 63;
            size_t g = base + (size_t)(k0 + kk) * D_MODEL + d;
            ks[kk][d] = K[g];
            vs[kk][d] = V[g];
        }
        __syncthreads();

        // scores: each thread does 8 (q,k) dot products, float4 over d
#pragma unroll
        for (int e = 0; e < 8; e++) {
            int idx = tid + 256 * e;
            int q = idx >> 5, k = idx & 31;
            const float4* q4 = (const float4*)qs[q];
            const float4* k4 = (const float4*)ks[k];
            float dot = 0.f;
#pragma unroll
            for (int d4 = 0; d4 < DK / 4; d4++) {
                float4 a = q4[d4], c = k4[d4];
                dot += a.x * c.x + a.y * c.y + a.z * c.z + a.w * c.w;
            }
            sc[q][k] = dot;
        }
        __syncthreads();

        // online softmax update (one thread per query)
        if (tid < QT) {
            const int q = tid;
            float mold = m_s[q];
            float mx = mold;
#pragma unroll
            for (int k = 0; k < KT; k++) mx = fmaxf(mx, sc[q][k]);
            float fs = __expf(mold - mx);
            float sum = 0.f;
#pragma unroll
            for (int k = 0; k < KT; k++) {
                float p = __expf(sc[q][k] - mx);
                sc[q][k] = p;
                sum += p;
            }
            m_s[q] = mx;
            l_s[q] = l_s[q] * fs + sum;
            f_s[q] = fs;
        }
        __syncthreads();

        // rescale accumulators and add P @ V
#pragma unroll
        for (int i = 0; i < 16; i++) o[i] *= f_s[qq * 16 + i];

#pragma unroll
        for (int k4i = 0; k4i < KT; k4i += 4) {
            float v0 = vs[k4i + 0][dd];
            float v1 = vs[k4i + 1][dd];
            float v2 = vs[k4i + 2][dd];
            float v3 = vs[k4i + 3][dd];
#pragma unroll
            for (int i = 0; i < 16; i++) {
                int q = qq * 16 + i;
                float4 p = *(const float4*)&sc[q][k4i];
                o[i] += p.x * v0 + p.y * v1 + p.z * v2 + p.w * v3;
            }
        }
        __syncthreads();
    }

    // normalize + write
#pragma unroll
    for (int i = 0; i < 16; i++) {
        int q = qq * 16 + i;
        O[base + (size_t)(q0 + q) * D_MODEL + dd] = o[i] / l_s[q];
    }
}

// ---------------------------------------------------------------------------
// LayerNorm over last dim (1024). One block (256 threads) per row.
// var = E[x^2] - E[x]^2 (ddof=0, matches jnp.var), eps = 1e-5.
// ---------------------------------------------------------------------------
__global__ __launch_bounds__(256)
void ln_kernel(const float* __restrict__ X, const float* __restrict__ g,
               const float* __restrict__ b, float* __restrict__ Y)
{
    const int row = blockIdx.x;
    const float* x = X + (size_t)row * D_MODEL;

    float v[4];
    float s = 0.f, s2 = 0.f;
#pragma unroll
    for (int e = 0; e < 4; e++) {
        v[e] = x[threadIdx.x + 256 * e];
        s  += v[e];
        s2 += v[e] * v[e];
    }
#pragma unroll
    for (int off = 16; off; off >>= 1) {
        s  += __shfl_xor_sync(0xffffffffu, s,  off);
        s2 += __shfl_xor_sync(0xffffffffu, s2, off);
    }
    __shared__ float rs[8], rs2[8];
    const int w = threadIdx.x >> 5, lane = threadIdx.x & 31;
    if (lane == 0) { rs[w] = s; rs2[w] = s2; }
    __syncthreads();
    s = 0.f; s2 = 0.f;
#pragma unroll
    for (int i = 0; i < 8; i++) { s += rs[i]; s2 += rs2[i]; }

    const float mean = s * (1.f / D_MODEL);
    const float var  = s2 * (1.f / D_MODEL) - mean * mean;
    const float rstd = rsqrtf(var + 1e-5f);

    float* y = Y + (size_t)row * D_MODEL;
#pragma unroll
    for (int e = 0; e < 4; e++) {
        int c = threadIdx.x + 256 * e;
        y[c] = (v[e] - mean) * rstd * g[c] + b[c];
    }
}

// ---------------------------------------------------------------------------
// Launch
// Inputs (metadata order): x, wq, bq, wk, bk, wv, bv, wo, bo,
//                          ln1_g, ln1_b, ln2_g, ln2_b, w1, b1, w2, b2
// ---------------------------------------------------------------------------
extern "C" void kernel_launch(void* const* d_in, const int* in_sizes, int n_in,
                              void* d_out, int out_size)
{
    const float* x     = (const float*)d_in[0];
    const float* wq    = (const float*)d_in[1];
    const float* bq    = (const float*)d_in[2];
    const float* wk    = (const float*)d_in[3];
    const float* bk    = (const float*)d_in[4];
    const float* wv    = (const float*)d_in[5];
    const float* bv    = (const float*)d_in[6];
    const float* wo    = (const float*)d_in[7];
    const float* bo    = (const float*)d_in[8];
    const float* ln1_g = (const float*)d_in[9];
    const float* ln1_b = (const float*)d_in[10];
    const float* ln2_g = (const float*)d_in[11];
    const float* ln2_b = (const float*)d_in[12];
    const float* w1    = (const float*)d_in[13];
    const float* b1    = (const float*)d_in[14];
    const float* w2    = (const float*)d_in[15];
    const float* b2    = (const float*)d_in[16];
    float* out = (float*)d_out;

    float *q, *k, *v, *attn, *x1, *tmp, *hbuf;
    cudaGetSymbolAddress((void**)&q,    g_q);
    cudaGetSymbolAddress((void**)&k,    g_k);
    cudaGetSymbolAddress((void**)&v,    g_v);
    cudaGetSymbolAddress((void**)&attn, g_attn);
    cudaGetSymbolAddress((void**)&x1,   g_x1);
    cudaGetSymbolAddress((void**)&tmp,  g_tmp);
    cudaGetSymbolAddress((void**)&hbuf, g_h);

    const dim3 blk(256);
    const dim3 grid_d (D_MODEL / BN, MTOT / BM);  // N=1024 GEMMs
    const dim3 grid_ff(DFF / BN,     MTOT / BM);  // N=4096 GEMM

    // QKV projections
    gemm_kernel<0><<<grid_d, blk>>>(x, wq, bq, nullptr, q, MTOT, D_MODEL, D_MODEL);
    gemm_kernel<0><<<grid_d, blk>>>(x, wk, bk, nullptr, k, MTOT, D_MODEL, D_MODEL);
    gemm_kernel<0><<<grid_d, blk>>>(x, wv, bv, nullptr, v, MTOT, D_MODEL, D_MODEL);

    // attention
    attn_kernel<<<dim3(SEQ / QT, BATCH * NH), blk>>>(q, k, v, attn);

    // out-proj + residual, then LN1 -> x1
    gemm_kernel<2><<<grid_d, blk>>>(attn, wo, bo, x, tmp, MTOT, D_MODEL, D_MODEL);
    ln_kernel<<<MTOT, blk>>>(tmp, ln1_g, ln1_b, x1);

    // FFN
    gemm_kernel<1><<<grid_ff, blk>>>(x1, w1, b1, nullptr, hbuf, MTOT, DFF, D_MODEL);
    gemm_kernel<2><<<grid_d, blk>>>(hbuf, w2, b2, x1, tmp, MTOT, D_MODEL, DFF);
    ln_kernel<<<MTOT, blk>>>(tmp, ln2_g, ln2_b, out);
}

// round 2
// speedup vs baseline: 1.6591x; 1.6591x over previous
#include <cuda_runtime.h>
#include <cstdint>
#include <cstddef>

// Problem dims (fixed by the reference)
#define D_MODEL 1024
#define SEQ     2048
#define BATCH   2
#define NH      16
#define DK      64
#define DFF     4096
#define MTOT    (BATCH * SEQ)   // 4096 rows

// ---------------------------------------------------------------------------
// Scratch (no allocation allowed -> __device__ globals)
// ---------------------------------------------------------------------------
__device__ float g_q   [MTOT * D_MODEL];
__device__ float g_k   [MTOT * D_MODEL];
__device__ float g_v   [MTOT * D_MODEL];
__device__ float g_attn[MTOT * D_MODEL];
__device__ float g_x1  [MTOT * D_MODEL];
__device__ float g_tmp [MTOT * D_MODEL];
__device__ float g_h   [MTOT * DFF];

// ---------------------------------------------------------------------------
// Tensor-core GEMM (tf32 mma.sync): C = A[MxK] @ W[KxN] + bias (+relu / +res)
// Block tile 128x128, K-tile 16, 256 threads = 8 warps in 2(M) x 4(N) grid,
// warp tile 64x32, mma m16n8k8 -> 4x4 mma tiles per warp per k8-step.
// Double-buffered smem, one __syncthreads per K-tile.
// Smem pitches: As pitch 20 (banks (20g+t)%32 all distinct),
//               Bs pitch 136 (banks (8t+g)%32 all distinct).
// EPI: 0 = bias, 1 = bias+relu, 2 = bias+res
// ---------------------------------------------------------------------------
__device__ __forceinline__ uint32_t f2tf32(float x) {
    uint32_t u;
    asm("cvt.rna.tf32.f32 %0, %1;" : "=r"(u) : "f"(x));
    return u;
}

__device__ __forceinline__ void mma_tf32(float c[4], const uint32_t a[4],
                                         const uint32_t b[2]) {
    asm("mma.sync.aligned.m16n8k8.row.col.f32.tf32.tf32.f32 "
        "{%0,%1,%2,%3}, {%4,%5,%6,%7}, {%8,%9}, {%0,%1,%2,%3};"
        : "+f"(c[0]), "+f"(c[1]), "+f"(c[2]), "+f"(c[3])
        : "r"(a[0]), "r"(a[1]), "r"(a[2]), "r"(a[3]), "r"(b[0]), "r"(b[1]));
}

#define BKT 16
#define APITCH 20
#define BPITCH 136

template <int EPI>
__global__ __launch_bounds__(256)
void gemm_tc(const float* __restrict__ A, const float* __restrict__ W,
             const float* __restrict__ bias, const float* __restrict__ res,
             float* __restrict__ C, int M, int N, int K)
{
    __shared__ uint32_t As[2][128][APITCH];
    __shared__ uint32_t Bs[2][BKT][BPITCH];

    const int tid  = threadIdx.x;
    const int bm   = blockIdx.y * 128;
    const int bn   = blockIdx.x * 128;
    const int wid  = tid >> 5;
    const int lane = tid & 31;
    const int g    = lane >> 2;     // 0..7
    const int t    = lane & 3;      // 0..3
    const int wm   = (wid & 1) * 64;
    const int wn   = (wid >> 1) * 32;

    float acc[4][4][4];
#pragma unroll
    for (int i = 0; i < 4; i++)
#pragma unroll
        for (int j = 0; j < 4; j++)
#pragma unroll
            for (int e = 0; e < 4; e++) acc[i][j][e] = 0.f;

    // gmem tile loader indexing (2 float4 per thread per tile, each array)
    const int a_r0 = (tid + 0)   >> 2, a_c0 = (tid + 0)   & 3;
    const int a_r1 = (tid + 256) >> 2, a_c1 = (tid + 256) & 3;
    const int b_r0 = (tid + 0)   >> 5, b_c0 = (tid + 0)   & 31;
    const int b_r1 = (tid + 256) >> 5, b_c1 = (tid + 256) & 31;

    float4 pa0, pa1, pb0, pb1;

#define LOAD_GMEM(k0)                                                          \
    pa0 = *(const float4*)(A + (size_t)(bm + a_r0) * K + (k0) + a_c0 * 4);     \
    pa1 = *(const float4*)(A + (size_t)(bm + a_r1) * K + (k0) + a_c1 * 4);     \
    pb0 = *(const float4*)(W + (size_t)((k0) + b_r0) * N + bn + b_c0 * 4);     \
    pb1 = *(const float4*)(W + (size_t)((k0) + b_r1) * N + bn + b_c1 * 4);

#define STORE_SMEM(bf)                                                         \
    As[bf][a_r0][a_c0 * 4 + 0] = f2tf32(pa0.x);                                \
    As[bf][a_r0][a_c0 * 4 + 1] = f2tf32(pa0.y);                                \
    As[bf][a_r0][a_c0 * 4 + 2] = f2tf32(pa0.z);                                \
    As[bf][a_r0][a_c0 * 4 + 3] = f2tf32(pa0.w);                                \
    As[bf][a_r1][a_c1 * 4 + 0] = f2tf32(pa1.x);                                \
    As[bf][a_r1][a_c1 * 4 + 1] = f2tf32(pa1.y);                                \
    As[bf][a_r1][a_c1 * 4 + 2] = f2tf32(pa1.z);                                \
    As[bf][a_r1][a_c1 * 4 + 3] = f2tf32(pa1.w);                                \
    Bs[bf][b_r0][b_c0 * 4 + 0] = f2tf32(pb0.x);                                \
    Bs[bf][b_r0][b_c0 * 4 + 1] = f2tf32(pb0.y);                                \
    Bs[bf][b_r0][b_c0 * 4 + 2] = f2tf32(pb0.z);                                \
    Bs[bf][b_r0][b_c0 * 4 + 3] = f2tf32(pb0.w);                                \
    Bs[bf][b_r1][b_c1 * 4 + 0] = f2tf32(pb1.x);                                \
    Bs[bf][b_r1][b_c1 * 4 + 1] = f2tf32(pb1.y);                                \
    Bs[bf][b_r1][b_c1 * 4 + 2] = f2tf32(pb1.z);                                \
    Bs[bf][b_r1][b_c1 * 4 + 3] = f2tf32(pb1.w);

    // prologue: tile 0 -> smem buf 0
    LOAD_GMEM(0)
    STORE_SMEM(0)
    __syncthreads();

    const int nk = K >> 4;
    int buf = 0;
    for (int kt = 0; kt < nk; kt++) {
        if (kt + 1 < nk) { LOAD_GMEM((kt + 1) * BKT) }

#pragma unroll
        for (int ks = 0; ks < BKT; ks += 8) {
            uint32_t af[4][4];
#pragma unroll
            for (int mt = 0; mt < 4; mt++) {
                const int r = wm + mt * 16 + g;
                af[mt][0] = As[buf][r    ][ks + t];
                af[mt][1] = As[buf][r + 8][ks + t];
                af[mt][2] = As[buf][r    ][ks + t + 4];
                af[mt][3] = As[buf][r + 8][ks + t + 4];
            }
            uint32_t bfr[4][2];
#pragma unroll
            for (int nt = 0; nt < 4; nt++) {
                const int c = wn + nt * 8 + g;
                bfr[nt][0] = Bs[buf][ks + t    ][c];
                bfr[nt][1] = Bs[buf][ks + t + 4][c];
            }
#pragma unroll
            for (int mt = 0; mt < 4; mt++)
#pragma unroll
                for (int nt = 0; nt < 4; nt++)
                    mma_tf32(acc[mt][nt], af[mt], bfr[nt]);
        }

        if (kt + 1 < nk) { STORE_SMEM(buf ^ 1) }
        __syncthreads();
        buf ^= 1;
    }

    // epilogue: c0,c1 -> row (g), cols 2t,2t+1 ; c2,c3 -> row (g+8)
#pragma unroll
    for (int mt = 0; mt < 4; mt++) {
        const int r = bm + wm + mt * 16 + g;
#pragma unroll
        for (int nt = 0; nt < 4; nt++) {
            const int c = bn + wn + nt * 8 + 2 * t;
            const float2 bb = *(const float2*)(bias + c);
            float2 v0, v1;
            v0.x = acc[mt][nt][0] + bb.x;  v0.y = acc[mt][nt][1] + bb.y;
            v1.x = acc[mt][nt][2] + bb.x;  v1.y = acc[mt][nt][3] + bb.y;
            if (EPI == 1) {
                v0.x = fmaxf(v0.x, 0.f); v0.y = fmaxf(v0.y, 0.f);
                v1.x = fmaxf(v1.x, 0.f); v1.y = fmaxf(v1.y, 0.f);
            }
            if (EPI == 2) {
                const float2 r0 = *(const float2*)(res + (size_t)r * N + c);
                const float2 r1 = *(const float2*)(res + (size_t)(r + 8) * N + c);
                v0.x += r0.x; v0.y += r0.y;
                v1.x += r1.x; v1.y += r1.y;
            }
            *(float2*)(C + (size_t)r * N + c)       = v0;
            *(float2*)(C + (size_t)(r + 8) * N + c) = v1;
        }
    }
}

// ---------------------------------------------------------------------------
// Flash attention, fp32. Grid: (SEQ/QT, BATCH*NH). 256 threads.
// ---------------------------------------------------------------------------
#define QT 64
#define KT 32
#define KPAD 68

__global__ __launch_bounds__(256)
void attn_kernel(const float* __restrict__ Q, const float* __restrict__ K,
                 const float* __restrict__ V, float* __restrict__ O)
{
    __shared__ float qs[QT][KPAD];
    __shared__ float ks[KT][KPAD];
    __shared__ float vs[KT][KPAD];
    __shared__ float sc[QT][KT];
    __shared__ float m_s[QT], l_s[QT], f_s[QT];

    const int tid = threadIdx.x;
    const int bh  = blockIdx.y;
    const int b   = bh >> 4;
    const int h   = bh & 15;
    const int q0  = blockIdx.x * QT;
    const float scale = 0.125f;  // 1/sqrt(64)

    const size_t base = (size_t)b * SEQ * D_MODEL + (size_t)h * DK;

#pragma unroll
    for (int e = 0; e < (QT * DK) / 256; e++) {
        int idx = tid + 256 * e;
        int qq = idx >> 6, d = idx & 63;
        qs[qq][d] = Q[base + (size_t)(q0 + qq) * D_MODEL + d] * scale;
    }
    if (tid < QT) { m_s[tid] = -1e30f; l_s[tid] = 0.f; }

    const int qq = tid >> 6;
    const int dd = tid & 63;
    float o[16];
#pragma unroll
    for (int i = 0; i < 16; i++) o[i] = 0.f;
    __syncthreads();

    for (int k0 = 0; k0 < SEQ; k0 += KT) {
#pragma unroll
        for (int e = 0; e < (KT * DK) / 256; e++) {
            int idx = tid + 256 * e;
            int kk = idx >> 6, d = idx & 63;
            size_t gm = base + (size_t)(k0 + kk) * D_MODEL + d;
            ks[kk][d] = K[gm];
            vs[kk][d] = V[gm];
        }
        __syncthreads();

#pragma unroll
        for (int e = 0; e < 8; e++) {
            int idx = tid + 256 * e;
            int q = idx >> 5, k = idx & 31;
            const float4* q4 = (const float4*)qs[q];
            const float4* k4 = (const float4*)ks[k];
            float dot = 0.f;
#pragma unroll
            for (int d4 = 0; d4 < DK / 4; d4++) {
                float4 a = q4[d4], c = k4[d4];
                dot += a.x * c.x + a.y * c.y + a.z * c.z + a.w * c.w;
            }
            sc[q][k] = dot;
        }
        __syncthreads();

        if (tid < QT) {
            const int q = tid;
            float mold = m_s[q];
            float mx = mold;
#pragma unroll
            for (int k = 0; k < KT; k++) mx = fmaxf(mx, sc[q][k]);
            float fs = __expf(mold - mx);
            float sum = 0.f;
#pragma unroll
            for (int k = 0; k < KT; k++) {
                float p = __expf(sc[q][k] - mx);
                sc[q][k] = p;
                sum += p;
            }
            m_s[q] = mx;
            l_s[q] = l_s[q] * fs + sum;
            f_s[q] = fs;
        }
        __syncthreads();

#pragma unroll
        for (int i = 0; i < 16; i++) o[i] *= f_s[qq * 16 + i];

#pragma unroll
        for (int k4i = 0; k4i < KT; k4i += 4) {
            float v0 = vs[k4i + 0][dd];
            float v1 = vs[k4i + 1][dd];
            float v2 = vs[k4i + 2][dd];
            float v3 = vs[k4i + 3][dd];
#pragma unroll
            for (int i = 0; i < 16; i++) {
                int q = qq * 16 + i;
                float4 p = *(const float4*)&sc[q][k4i];
                o[i] += p.x * v0 + p.y * v1 + p.z * v2 + p.w * v3;
            }
        }
        __syncthreads();
    }

#pragma unroll
    for (int i = 0; i < 16; i++) {
        int q = qq * 16 + i;
        O[base + (size_t)(q0 + q) * D_MODEL + dd] = o[i] / l_s[q];
    }
}

// ---------------------------------------------------------------------------
// LayerNorm over last dim (1024). One block (256 threads) per row.
// ---------------------------------------------------------------------------
__global__ __launch_bounds__(256)
void ln_kernel(const float* __restrict__ X, const float* __restrict__ g,
               const float* __restrict__ b, float* __restrict__ Y)
{
    const int row = blockIdx.x;
    const float* x = X + (size_t)row * D_MODEL;

    float v[4];
    float s = 0.f, s2 = 0.f;
#pragma unroll
    for (int e = 0; e < 4; e++) {
        v[e] = x[threadIdx.x + 256 * e];
        s  += v[e];
        s2 += v[e] * v[e];
    }
#pragma unroll
    for (int off = 16; off; off >>= 1) {
        s  += __shfl_xor_sync(0xffffffffu, s,  off);
        s2 += __shfl_xor_sync(0xffffffffu, s2, off);
    }
    __shared__ float rs[8], rs2[8];
    const int w = threadIdx.x >> 5, lane = threadIdx.x & 31;
    if (lane == 0) { rs[w] = s; rs2[w] = s2; }
    __syncthreads();
    s = 0.f; s2 = 0.f;
#pragma unroll
    for (int i = 0; i < 8; i++) { s += rs[i]; s2 += rs2[i]; }

    const float mean = s * (1.f / D_MODEL);
    const float var  = s2 * (1.f / D_MODEL) - mean * mean;
    const float rstd = rsqrtf(var + 1e-5f);

    float* y = Y + (size_t)row * D_MODEL;
#pragma unroll
    for (int e = 0; e < 4; e++) {
        int c = threadIdx.x + 256 * e;
        y[c] = (v[e] - mean) * rstd * g[c] + b[c];
    }
}

// ---------------------------------------------------------------------------
// Launch
// Inputs (metadata order): x, wq, bq, wk, bk, wv, bv, wo, bo,
//                          ln1_g, ln1_b, ln2_g, ln2_b, w1, b1, w2, b2
// ---------------------------------------------------------------------------
extern "C" void kernel_launch(void* const* d_in, const int* in_sizes, int n_in,
                              void* d_out, int out_size)
{
    const float* x     = (const float*)d_in[0];
    const float* wq    = (const float*)d_in[1];
    const float* bq    = (const float*)d_in[2];
    const float* wk    = (const float*)d_in[3];
    const float* bk    = (const float*)d_in[4];
    const float* wv    = (const float*)d_in[5];
    const float* bv    = (const float*)d_in[6];
    const float* wo    = (const float*)d_in[7];
    const float* bo    = (const float*)d_in[8];
    const float* ln1_g = (const float*)d_in[9];
    const float* ln1_b = (const float*)d_in[10];
    const float* ln2_g = (const float*)d_in[11];
    const float* ln2_b = (const float*)d_in[12];
    const float* w1    = (const float*)d_in[13];
    const float* b1    = (const float*)d_in[14];
    const float* w2    = (const float*)d_in[15];
    const float* b2    = (const float*)d_in[16];
    float* out = (float*)d_out;

    float *q, *k, *v, *attn, *x1, *tmp, *hbuf;
    cudaGetSymbolAddress((void**)&q,    g_q);
    cudaGetSymbolAddress((void**)&k,    g_k);
    cudaGetSymbolAddress((void**)&v,    g_v);
    cudaGetSymbolAddress((void**)&attn, g_attn);
    cudaGetSymbolAddress((void**)&x1,   g_x1);
    cudaGetSymbolAddress((void**)&tmp,  g_tmp);
    cudaGetSymbolAddress((void**)&hbuf, g_h);

    const dim3 blk(256);
    const dim3 grid_d (D_MODEL / 128, MTOT / 128);  // 8 x 32
    const dim3 grid_ff(DFF / 128,     MTOT / 128);  // 32 x 32

    // QKV projections (tensor cores)
    gemm_tc<0><<<grid_d, blk>>>(x, wq, bq, nullptr, q, MTOT, D_MODEL, D_MODEL);
    gemm_tc<0><<<grid_d, blk>>>(x, wk, bk, nullptr, k, MTOT, D_MODEL, D_MODEL);
    gemm_tc<0><<<grid_d, blk>>>(x, wv, bv, nullptr, v, MTOT, D_MODEL, D_MODEL);

    // attention
    attn_kernel<<<dim3(SEQ / QT, BATCH * NH), blk>>>(q, k, v, attn);

    // out-proj + residual, then LN1 -> x1
    gemm_tc<2><<<grid_d, blk>>>(attn, wo, bo, x, tmp, MTOT, D_MODEL, D_MODEL);
    ln_kernel<<<MTOT, blk>>>(tmp, ln1_g, ln1_b, x1);

    // FFN
    gemm_tc<1><<<grid_ff, blk>>>(x1, w1, b1, nullptr, hbuf, MTOT, DFF, D_MODEL);
    gemm_tc<2><<<grid_d, blk>>>(hbuf, w2, b2, x1, tmp, MTOT, D_MODEL, DFF);
    ln_kernel<<<MTOT, blk>>>(tmp, ln2_g, ln2_b, out);
}

// round 3
// speedup vs baseline: 3.7017x; 2.2311x over previous
#include <cuda_runtime.h>
#include <cstdint>
#include <cstddef>

// Problem dims (fixed by the reference)
#define D_MODEL 1024
#define SEQ     2048
#define BATCH   2
#define NH      16
#define DK      64
#define DFF     4096
#define MTOT    (BATCH * SEQ)   // 4096 rows

// ---------------------------------------------------------------------------
// Scratch (no allocation allowed -> __device__ globals)
// ---------------------------------------------------------------------------
__device__ float g_q   [MTOT * D_MODEL];
__device__ float g_k   [MTOT * D_MODEL];
__device__ float g_v   [MTOT * D_MODEL];
__device__ float g_attn[MTOT * D_MODEL];
__device__ float g_x1  [MTOT * D_MODEL];
__device__ float g_tmp [MTOT * D_MODEL];
__device__ float g_h   [MTOT * DFF];

// ---------------------------------------------------------------------------
// tf32 helpers (mma.sync m16n8k8)
// ---------------------------------------------------------------------------
__device__ __forceinline__ uint32_t f2tf32(float x) {
    uint32_t u;
    asm("cvt.rna.tf32.f32 %0, %1;" : "=r"(u) : "f"(x));
    return u;
}

__device__ __forceinline__ void mma_tf32(float c[4], const uint32_t a[4],
                                         const uint32_t b[2]) {
    asm("mma.sync.aligned.m16n8k8.row.col.f32.tf32.tf32.f32 "
        "{%0,%1,%2,%3}, {%4,%5,%6,%7}, {%8,%9}, {%0,%1,%2,%3};"
        : "+f"(c[0]), "+f"(c[1]), "+f"(c[2]), "+f"(c[3])
        : "r"(a[0]), "r"(a[1]), "r"(a[2]), "r"(a[3]), "r"(b[0]), "r"(b[1]));
}

// ---------------------------------------------------------------------------
// Tensor-core GEMM (unchanged from R2 — passing at ~95 TF/s)
// ---------------------------------------------------------------------------
#define BKT 16
#define APITCH 20
#define BPITCH 136

template <int EPI>
__global__ __launch_bounds__(256)
void gemm_tc(const float* __restrict__ A, const float* __restrict__ W,
             const float* __restrict__ bias, const float* __restrict__ res,
             float* __restrict__ C, int M, int N, int K)
{
    __shared__ uint32_t As[2][128][APITCH];
    __shared__ uint32_t Bs[2][BKT][BPITCH];

    const int tid  = threadIdx.x;
    const int bm   = blockIdx.y * 128;
    const int bn   = blockIdx.x * 128;
    const int wid  = tid >> 5;
    const int lane = tid & 31;
    const int g    = lane >> 2;
    const int t    = lane & 3;
    const int wm   = (wid & 1) * 64;
    const int wn   = (wid >> 1) * 32;

    float acc[4][4][4];
#pragma unroll
    for (int i = 0; i < 4; i++)
#pragma unroll
        for (int j = 0; j < 4; j++)
#pragma unroll
            for (int e = 0; e < 4; e++) acc[i][j][e] = 0.f;

    const int a_r0 = (tid + 0)   >> 2, a_c0 = (tid + 0)   & 3;
    const int a_r1 = (tid + 256) >> 2, a_c1 = (tid + 256) & 3;
    const int b_r0 = (tid + 0)   >> 5, b_c0 = (tid + 0)   & 31;
    const int b_r1 = (tid + 256) >> 5, b_c1 = (tid + 256) & 31;

    float4 pa0, pa1, pb0, pb1;

#define LOAD_GMEM(k0)                                                          \
    pa0 = *(const float4*)(A + (size_t)(bm + a_r0) * K + (k0) + a_c0 * 4);     \
    pa1 = *(const float4*)(A + (size_t)(bm + a_r1) * K + (k0) + a_c1 * 4);     \
    pb0 = *(const float4*)(W + (size_t)((k0) + b_r0) * N + bn + b_c0 * 4);     \
    pb1 = *(const float4*)(W + (size_t)((k0) + b_r1) * N + bn + b_c1 * 4);

#define STORE_SMEM(bf)                                                         \
    As[bf][a_r0][a_c0 * 4 + 0] = f2tf32(pa0.x);                                \
    As[bf][a_r0][a_c0 * 4 + 1] = f2tf32(pa0.y);                                \
    As[bf][a_r0][a_c0 * 4 + 2] = f2tf32(pa0.z);                                \
    As[bf][a_r0][a_c0 * 4 + 3] = f2tf32(pa0.w);                                \
    As[bf][a_r1][a_c1 * 4 + 0] = f2tf32(pa1.x);                                \
    As[bf][a_r1][a_c1 * 4 + 1] = f2tf32(pa1.y);                                \
    As[bf][a_r1][a_c1 * 4 + 2] = f2tf32(pa1.z);                                \
    As[bf][a_r1][a_c1 * 4 + 3] = f2tf32(pa1.w);                                \
    Bs[bf][b_r0][b_c0 * 4 + 0] = f2tf32(pb0.x);                                \
    Bs[bf][b_r0][b_c0 * 4 + 1] = f2tf32(pb0.y);                                \
    Bs[bf][b_r0][b_c0 * 4 + 2] = f2tf32(pb0.z);                                \
    Bs[bf][b_r0][b_c0 * 4 + 3] = f2tf32(pb0.w);                                \
    Bs[bf][b_r1][b_c1 * 4 + 0] = f2tf32(pb1.x);                                \
    Bs[bf][b_r1][b_c1 * 4 + 1] = f2tf32(pb1.y);                                \
    Bs[bf][b_r1][b_c1 * 4 + 2] = f2tf32(pb1.z);                                \
    Bs[bf][b_r1][b_c1 * 4 + 3] = f2tf32(pb1.w);

    LOAD_GMEM(0)
    STORE_SMEM(0)
    __syncthreads();

    const int nk = K >> 4;
    int buf = 0;
    for (int kt = 0; kt < nk; kt++) {
        if (kt + 1 < nk) { LOAD_GMEM((kt + 1) * BKT) }

#pragma unroll
        for (int ks = 0; ks < BKT; ks += 8) {
            uint32_t af[4][4];
#pragma unroll
            for (int mt = 0; mt < 4; mt++) {
                const int r = wm + mt * 16 + g;
                af[mt][0] = As[buf][r    ][ks + t];
                af[mt][1] = As[buf][r + 8][ks + t];
                af[mt][2] = As[buf][r    ][ks + t + 4];
                af[mt][3] = As[buf][r + 8][ks + t + 4];
            }
            uint32_t bfr[4][2];
#pragma unroll
            for (int nt = 0; nt < 4; nt++) {
                const int c = wn + nt * 8 + g;
                bfr[nt][0] = Bs[buf][ks + t    ][c];
                bfr[nt][1] = Bs[buf][ks + t + 4][c];
            }
#pragma unroll
            for (int mt = 0; mt < 4; mt++)
#pragma unroll
                for (int nt = 0; nt < 4; nt++)
                    mma_tf32(acc[mt][nt], af[mt], bfr[nt]);
        }

        if (kt + 1 < nk) { STORE_SMEM(buf ^ 1) }
        __syncthreads();
        buf ^= 1;
    }

#pragma unroll
    for (int mt = 0; mt < 4; mt++) {
        const int r = bm + wm + mt * 16 + g;
#pragma unroll
        for (int nt = 0; nt < 4; nt++) {
            const int c = bn + wn + nt * 8 + 2 * t;
            const float2 bb = *(const float2*)(bias + c);
            float2 v0, v1;
            v0.x = acc[mt][nt][0] + bb.x;  v0.y = acc[mt][nt][1] + bb.y;
            v1.x = acc[mt][nt][2] + bb.x;  v1.y = acc[mt][nt][3] + bb.y;
            if (EPI == 1) {
                v0.x = fmaxf(v0.x, 0.f); v0.y = fmaxf(v0.y, 0.f);
                v1.x = fmaxf(v1.x, 0.f); v1.y = fmaxf(v1.y, 0.f);
            }
            if (EPI == 2) {
                const float2 r0 = *(const float2*)(res + (size_t)r * N + c);
                const float2 r1 = *(const float2*)(res + (size_t)(r + 8) * N + c);
                v0.x += r0.x; v0.y += r0.y;
                v1.x += r1.x; v1.y += r1.y;
            }
            *(float2*)(C + (size_t)r * N + c)       = v0;
            *(float2*)(C + (size_t)(r + 8) * N + c) = v1;
        }
    }
}

// ---------------------------------------------------------------------------
// Tensor-core flash attention (tf32 mma).
// Block: 128 queries, 8 warps; each warp owns 16 query rows (full softmax row
// lives in one warp -> stats reduce over the 4-lane t-group only).
// Inner tile: 64 keys. S in registers -> online softmax in registers ->
// P through padded smem -> PV mma.
// Pitches: qs/ks/ps 68 (banks 4g+t bijective), vs 72 (banks 8t+g bijective).
// ---------------------------------------------------------------------------
#define AQT 128
#define AKT 64
#define QP  68
#define KP  68
#define VP  72
#define PP  68
#define QS_OFF 0
#define KS_OFF (AQT * QP)            // 8704
#define VS_OFF (KS_OFF + AKT * KP)   // 13056
#define PS_OFF (VS_OFF + AKT * VP)   // 17664
#define ATTN_SMEM_BYTES ((PS_OFF + AQT * PP) * 4)   // 105472

__global__ __launch_bounds__(256, 2)
void attn_tc(const float* __restrict__ Q, const float* __restrict__ K,
             const float* __restrict__ V, float* __restrict__ O)
{
    extern __shared__ uint32_t sm_[];
    uint32_t* qs = sm_ + QS_OFF;
    uint32_t* ks = sm_ + KS_OFF;
    uint32_t* vs = sm_ + VS_OFF;
    uint32_t* ps = sm_ + PS_OFF;

    const int tid  = threadIdx.x;
    const int wid  = tid >> 5;
    const int lane = tid & 31;
    const int g    = lane >> 2;
    const int t    = lane & 3;
    const int bh   = blockIdx.y;
    const int b    = bh >> 4;
    const int h    = bh & 15;
    const int q0   = blockIdx.x * AQT;
    const size_t base = (size_t)b * SEQ * D_MODEL + (size_t)h * DK;

    // load Q tile (scaled by 1/sqrt(64), tf32)
#pragma unroll
    for (int e = 0; e < 8; e++) {
        int idx = tid + 256 * e;            // 2048 float4s
        int r = idx >> 4, c4 = (idx & 15) * 4;
        float4 qv = *(const float4*)(Q + base + (size_t)(q0 + r) * D_MODEL + c4);
        qs[r * QP + c4 + 0] = f2tf32(qv.x * 0.125f);
        qs[r * QP + c4 + 1] = f2tf32(qv.y * 0.125f);
        qs[r * QP + c4 + 2] = f2tf32(qv.z * 0.125f);
        qs[r * QP + c4 + 3] = f2tf32(qv.w * 0.125f);
    }

    float m0 = -1e30f, m1 = -1e30f, l0 = 0.f, l1 = 0.f;
    float oacc[8][4];
#pragma unroll
    for (int nt = 0; nt < 8; nt++)
#pragma unroll
        for (int e = 0; e < 4; e++) oacc[nt][e] = 0.f;

    const int qrow = wid * 16;

    for (int k0 = 0; k0 < SEQ; k0 += AKT) {
        __syncthreads();   // protect ks/vs from previous iteration's readers
#pragma unroll
        for (int e = 0; e < 4; e++) {
            int idx = tid + 256 * e;        // 1024 float4s per array
            int r = idx >> 4, c4 = (idx & 15) * 4;
            float4 kv = *(const float4*)(K + base + (size_t)(k0 + r) * D_MODEL + c4);
            ks[r * KP + c4 + 0] = f2tf32(kv.x);
            ks[r * KP + c4 + 1] = f2tf32(kv.y);
            ks[r * KP + c4 + 2] = f2tf32(kv.z);
            ks[r * KP + c4 + 3] = f2tf32(kv.w);
            float4 vv = *(const float4*)(V + base + (size_t)(k0 + r) * D_MODEL + c4);
            vs[r * VP + c4 + 0] = f2tf32(vv.x);
            vs[r * VP + c4 + 1] = f2tf32(vv.y);
            vs[r * VP + c4 + 2] = f2tf32(vv.z);
            vs[r * VP + c4 + 3] = f2tf32(vv.w);
        }
        __syncthreads();

        // ---- S = Q K^T : warp tile m16 x n64, k = 64 ----
        float sacc[8][4];
#pragma unroll
        for (int nt = 0; nt < 8; nt++)
#pragma unroll
            for (int e = 0; e < 4; e++) sacc[nt][e] = 0.f;

#pragma unroll
        for (int k8 = 0; k8 < 8; k8++) {
            uint32_t a[4];
            a[0] = qs[(qrow + g    ) * QP + k8 * 8 + t];
            a[1] = qs[(qrow + g + 8) * QP + k8 * 8 + t];
            a[2] = qs[(qrow + g    ) * QP + k8 * 8 + t + 4];
            a[3] = qs[(qrow + g + 8) * QP + k8 * 8 + t + 4];
#pragma unroll
            for (int nt = 0; nt < 8; nt++) {
                uint32_t bb[2];
                bb[0] = ks[(nt * 8 + g) * KP + k8 * 8 + t];
                bb[1] = ks[(nt * 8 + g) * KP + k8 * 8 + t + 4];
                mma_tf32(sacc[nt], a, bb);
            }
        }

        // ---- online softmax (rows qrow+g and qrow+g+8) ----
        float rmax0 = -1e30f, rmax1 = -1e30f;
#pragma unroll
        for (int nt = 0; nt < 8; nt++) {
            rmax0 = fmaxf(rmax0, fmaxf(sacc[nt][0], sacc[nt][1]));
            rmax1 = fmaxf(rmax1, fmaxf(sacc[nt][2], sacc[nt][3]));
        }
        rmax0 = fmaxf(rmax0, __shfl_xor_sync(0xffffffffu, rmax0, 1));
        rmax0 = fmaxf(rmax0, __shfl_xor_sync(0xffffffffu, rmax0, 2));
        rmax1 = fmaxf(rmax1, __shfl_xor_sync(0xffffffffu, rmax1, 1));
        rmax1 = fmaxf(rmax1, __shfl_xor_sync(0xffffffffu, rmax1, 2));

        const float nm0 = fmaxf(m0, rmax0);
        const float nm1 = fmaxf(m1, rmax1);
        const float sc0 = __expf(m0 - nm0);
        const float sc1 = __expf(m1 - nm1);

        float rs0 = 0.f, rs1 = 0.f;
#pragma unroll
        for (int nt = 0; nt < 8; nt++) {
            float p00 = __expf(sacc[nt][0] - nm0);
            float p01 = __expf(sacc[nt][1] - nm0);
            float p10 = __expf(sacc[nt][2] - nm1);
            float p11 = __expf(sacc[nt][3] - nm1);
            rs0 += p00 + p01;
            rs1 += p10 + p11;
            ps[(qrow + g    ) * PP + nt * 8 + 2 * t    ] = f2tf32(p00);
            ps[(qrow + g    ) * PP + nt * 8 + 2 * t + 1] = f2tf32(p01);
            ps[(qrow + g + 8) * PP + nt * 8 + 2 * t    ] = f2tf32(p10);
            ps[(qrow + g + 8) * PP + nt * 8 + 2 * t + 1] = f2tf32(p11);
        }
        rs0 += __shfl_xor_sync(0xffffffffu, rs0, 1);
        rs0 += __shfl_xor_sync(0xffffffffu, rs0, 2);
        rs1 += __shfl_xor_sync(0xffffffffu, rs1, 1);
        rs1 += __shfl_xor_sync(0xffffffffu, rs1, 2);

        m0 = nm0; m1 = nm1;
        l0 = l0 * sc0 + rs0;
        l1 = l1 * sc1 + rs1;
#pragma unroll
        for (int nt = 0; nt < 8; nt++) {
            oacc[nt][0] *= sc0; oacc[nt][1] *= sc0;
            oacc[nt][2] *= sc1; oacc[nt][3] *= sc1;
        }

        __syncwarp();   // ps written/read within the warp only

        // ---- O += P V : A = ps rows (warp-local), B = vs ----
#pragma unroll
        for (int k8 = 0; k8 < 8; k8++) {
            uint32_t a[4];
            a[0] = ps[(qrow + g    ) * PP + k8 * 8 + t];
            a[1] = ps[(qrow + g + 8) * PP + k8 * 8 + t];
            a[2] = ps[(qrow + g    ) * PP + k8 * 8 + t + 4];
            a[3] = ps[(qrow + g + 8) * PP + k8 * 8 + t + 4];
#pragma unroll
            for (int nt = 0; nt < 8; nt++) {
                uint32_t bb[2];
                bb[0] = vs[(k8 * 8 + t    ) * VP + nt * 8 + g];
                bb[1] = vs[(k8 * 8 + t + 4) * VP + nt * 8 + g];
                mma_tf32(oacc[nt], a, bb);
            }
        }
    }

    // epilogue: normalize and store
    const float il0 = 1.f / l0;
    const float il1 = 1.f / l1;
#pragma unroll
    for (int nt = 0; nt < 8; nt++) {
        const int c = nt * 8 + 2 * t;
        float2 v0, v1;
        v0.x = oacc[nt][0] * il0;  v0.y = oacc[nt][1] * il0;
        v1.x = oacc[nt][2] * il1;  v1.y = oacc[nt][3] * il1;
        *(float2*)(O + base + (size_t)(q0 + qrow + g    ) * D_MODEL + c) = v0;
        *(float2*)(O + base + (size_t)(q0 + qrow + g + 8) * D_MODEL + c) = v1;
    }
}

// ---------------------------------------------------------------------------
// LayerNorm over last dim (1024). One block (256 threads) per row.
// ---------------------------------------------------------------------------
__global__ __launch_bounds__(256)
void ln_kernel(const float* __restrict__ X, const float* __restrict__ g,
               const float* __restrict__ b, float* __restrict__ Y)
{
    const int row = blockIdx.x;
    const float* x = X + (size_t)row * D_MODEL;

    float v[4];
    float s = 0.f, s2 = 0.f;
#pragma unroll
    for (int e = 0; e < 4; e++) {
        v[e] = x[threadIdx.x + 256 * e];
        s  += v[e];
        s2 += v[e] * v[e];
    }
#pragma unroll
    for (int off = 16; off; off >>= 1) {
        s  += __shfl_xor_sync(0xffffffffu, s,  off);
        s2 += __shfl_xor_sync(0xffffffffu, s2, off);
    }
    __shared__ float rs[8], rs2[8];
    const int w = threadIdx.x >> 5, lane = threadIdx.x & 31;
    if (lane == 0) { rs[w] = s; rs2[w] = s2; }
    __syncthreads();
    s = 0.f; s2 = 0.f;
#pragma unroll
    for (int i = 0; i < 8; i++) { s += rs[i]; s2 += rs2[i]; }

    const float mean = s * (1.f / D_MODEL);
    const float var  = s2 * (1.f / D_MODEL) - mean * mean;
    const float rstd = rsqrtf(var + 1e-5f);

    float* y = Y + (size_t)row * D_MODEL;
#pragma unroll
    for (int e = 0; e < 4; e++) {
        int c = threadIdx.x + 256 * e;
        y[c] = (v[e] - mean) * rstd * g[c] + b[c];
    }
}

// ---------------------------------------------------------------------------
// Launch
// ---------------------------------------------------------------------------
extern "C" void kernel_launch(void* const* d_in, const int* in_sizes, int n_in,
                              void* d_out, int out_size)
{
    const float* x     = (const float*)d_in[0];
    const float* wq    = (const float*)d_in[1];
    const float* bq    = (const float*)d_in[2];
    const float* wk    = (const float*)d_in[3];
    const float* bk    = (const float*)d_in[4];
    const float* wv    = (const float*)d_in[5];
    const float* bv    = (const float*)d_in[6];
    const float* wo    = (const float*)d_in[7];
    const float* bo    = (const float*)d_in[8];
    const float* ln1_g = (const float*)d_in[9];
    const float* ln1_b = (const float*)d_in[10];
    const float* ln2_g = (const float*)d_in[11];
    const float* ln2_b = (const float*)d_in[12];
    const float* w1    = (const float*)d_in[13];
    const float* b1    = (const float*)d_in[14];
    const float* w2    = (const float*)d_in[15];
    const float* b2    = (const float*)d_in[16];
    float* out = (float*)d_out;

    float *q, *k, *v, *attn, *x1, *tmp, *hbuf;
    cudaGetSymbolAddress((void**)&q,    g_q);
    cudaGetSymbolAddress((void**)&k,    g_k);
    cudaGetSymbolAddress((void**)&v,    g_v);
    cudaGetSymbolAddress((void**)&attn, g_attn);
    cudaGetSymbolAddress((void**)&x1,   g_x1);
    cudaGetSymbolAddress((void**)&tmp,  g_tmp);
    cudaGetSymbolAddress((void**)&hbuf, g_h);

    // opt in to >48KB dynamic smem for attention (idempotent, capture-safe)
    cudaFuncSetAttribute(attn_tc, cudaFuncAttributeMaxDynamicSharedMemorySize,
                         ATTN_SMEM_BYTES);

    const dim3 blk(256);
    const dim3 grid_d (D_MODEL / 128, MTOT / 128);
    const dim3 grid_ff(DFF / 128,     MTOT / 128);

    gemm_tc<0><<<grid_d, blk>>>(x, wq, bq, nullptr, q, MTOT, D_MODEL, D_MODEL);
    gemm_tc<0><<<grid_d, blk>>>(x, wk, bk, nullptr, k, MTOT, D_MODEL, D_MODEL);
    gemm_tc<0><<<grid_d, blk>>>(x, wv, bv, nullptr, v, MTOT, D_MODEL, D_MODEL);

    attn_tc<<<dim3(SEQ / AQT, BATCH * NH), blk, ATTN_SMEM_BYTES>>>(q, k, v, attn);

    gemm_tc<2><<<grid_d, blk>>>(attn, wo, bo, x, tmp, MTOT, D_MODEL, D_MODEL);
    ln_kernel<<<MTOT, blk>>>(tmp, ln1_g, ln1_b, x1);

    gemm_tc<1><<<grid_ff, blk>>>(x1, w1, b1, nullptr, hbuf, MTOT, DFF, D_MODEL);
    gemm_tc<2><<<grid_d, blk>>>(hbuf, w2, b2, x1, tmp, MTOT, D_MODEL, DFF);
    ln_kernel<<<MTOT, blk>>>(tmp, ln2_g, ln2_b, out);
}

// round 4
// speedup vs baseline: 3.9086x; 1.0559x over previous
#include <cuda_runtime.h>
#include <cstdint>
#include <cstddef>

// Problem dims (fixed by the reference)
#define D_MODEL 1024
#define SEQ     2048
#define BATCH   2
#define NH      16
#define DK      64
#define DFF     4096
#define MTOT    (BATCH * SEQ)   // 4096 rows

// ---------------------------------------------------------------------------
// Scratch (no allocation allowed -> __device__ globals)
// ---------------------------------------------------------------------------
__device__ float g_q   [MTOT * D_MODEL];
__device__ float g_k   [MTOT * D_MODEL];
__device__ float g_v   [MTOT * D_MODEL];
__device__ float g_attn[MTOT * D_MODEL];
__device__ float g_x1  [MTOT * D_MODEL];
__device__ float g_tmp [MTOT * D_MODEL];
__device__ float g_h   [MTOT * DFF];

// ---------------------------------------------------------------------------
// tf32 helpers (mma.sync m16n8k8)
// ---------------------------------------------------------------------------
__device__ __forceinline__ uint32_t f2tf32(float x) {
    uint32_t u;
    asm("cvt.rna.tf32.f32 %0, %1;" : "=r"(u) : "f"(x));
    return u;
}

__device__ __forceinline__ void mma_tf32(float c[4], const uint32_t a[4],
                                         const uint32_t b[2]) {
    asm("mma.sync.aligned.m16n8k8.row.col.f32.tf32.tf32.f32 "
        "{%0,%1,%2,%3}, {%4,%5,%6,%7}, {%8,%9}, {%0,%1,%2,%3};"
        : "+f"(c[0]), "+f"(c[1]), "+f"(c[2]), "+f"(c[3])
        : "r"(a[0]), "r"(a[1]), "r"(a[2]), "r"(a[3]), "r"(b[0]), "r"(b[1]));
}

__device__ __forceinline__ void cp16(uint32_t saddr, const void* gptr) {
    asm volatile("cp.async.cg.shared.global [%0], [%1], 16;"
                 :: "r"(saddr), "l"(gptr));
}
__device__ __forceinline__ void cp_commit() {
    asm volatile("cp.async.commit_group;");
}
__device__ __forceinline__ void cp_wait2() {
    asm volatile("cp.async.wait_group 2;");
}

// ---------------------------------------------------------------------------
// Tensor-core GEMM, cp.async 4-stage pipeline.
// Block tile 128x128, K-tile 16, 256 threads = 8 warps (2M x 4N), warp tile
// 64x32, mma m16n8k8. Smem: fp32 tiles, pitches 20 (A) / 136 (B) ->
// conflict-free fragment LDS; cvt to tf32 in registers before mma.
// EPI: 0 = bias, 1 = bias+relu, 2 = bias+res
// ---------------------------------------------------------------------------
#define GSTAGES 4
#define AS_STRIDE (128 * 20)    // words per A stage = 2560
#define BS_STRIDE (16 * 136)    // words per B stage = 2176
#define GEMM_SMEM_WORDS (GSTAGES * (AS_STRIDE + BS_STRIDE))
#define GEMM_SMEM_BYTES (GEMM_SMEM_WORDS * 4)   // 75776

template <int EPI>
__global__ __launch_bounds__(256, 2)
void gemm_tc(const float* __restrict__ A, const float* __restrict__ W,
             const float* __restrict__ bias, const float* __restrict__ res,
             float* __restrict__ C, int M, int N, int K)
{
    extern __shared__ float sm[];
    float* asm_ = sm;                          // [4][128][20]
    float* bsm_ = sm + GSTAGES * AS_STRIDE;    // [4][16][136]

    const int tid  = threadIdx.x;
    const int bm   = blockIdx.y * 128;
    const int bn   = blockIdx.x * 128;
    const int wid  = tid >> 5;
    const int lane = tid & 31;
    const int g    = lane >> 2;
    const int t    = lane & 3;
    const int wm   = (wid & 1) * 64;
    const int wn   = (wid >> 1) * 32;

    // cp.async lane assignment: A chunks (512 = 128r x 4c4): tid and tid+256
    const int a_r = tid >> 2, a_c = tid & 3;           // + (r+64, c)
    const int b_r = tid >> 5, b_c = tid & 31;          // + (r+8,  c)

    const uint32_t smem_base = (uint32_t)__cvta_generic_to_shared(sm);
    const uint32_t aS0 = smem_base + (a_r * 20 + a_c * 4) * 4;
    const uint32_t bS0 = smem_base + (GSTAGES * AS_STRIDE + b_r * 136 + b_c * 4) * 4;
    const float* aG0 = A + (size_t)(bm + a_r) * K + a_c * 4;
    const float* aG1 = A + (size_t)(bm + a_r + 64) * K + a_c * 4;
    const float* bG0 = W + (size_t)b_r * N + bn + b_c * 4;
    const float* bG1 = W + (size_t)(b_r + 8) * N + bn + b_c * 4;

    float acc[4][4][4];
#pragma unroll
    for (int i = 0; i < 4; i++)
#pragma unroll
        for (int j = 0; j < 4; j++)
#pragma unroll
            for (int e = 0; e < 4; e++) acc[i][j][e] = 0.f;

#define G_ISSUE(kt)                                                            \
    {                                                                          \
        const int _s = (kt) & 3;                                               \
        const int _k0 = (kt) * 16;                                             \
        cp16(aS0 + _s * (AS_STRIDE * 4), aG0 + _k0);                           \
        cp16(aS0 + _s * (AS_STRIDE * 4) + 64 * 20 * 4, aG1 + _k0);             \
        cp16(bS0 + _s * (BS_STRIDE * 4), bG0 + (size_t)_k0 * N);               \
        cp16(bS0 + _s * (BS_STRIDE * 4) + 8 * 136 * 4, bG1 + (size_t)_k0 * N); \
    }

    const int nk = K >> 4;
    // prologue: stages 0..2
#pragma unroll
    for (int s = 0; s < GSTAGES - 1; s++) { G_ISSUE(s) cp_commit(); }

    for (int kt = 0; kt < nk; kt++) {
        cp_wait2();
        __syncthreads();
        if (kt + GSTAGES - 1 < nk) { G_ISSUE(kt + GSTAGES - 1) }
        cp_commit();

        const float* as = asm_ + (kt & 3) * AS_STRIDE;
        const float* bs = bsm_ + (kt & 3) * BS_STRIDE;
#pragma unroll
        for (int ks = 0; ks < 16; ks += 8) {
            uint32_t af[4][4];
#pragma unroll
            for (int mt = 0; mt < 4; mt++) {
                const int r = wm + mt * 16 + g;
                af[mt][0] = f2tf32(as[r * 20 + ks + t]);
                af[mt][1] = f2tf32(as[(r + 8) * 20 + ks + t]);
                af[mt][2] = f2tf32(as[r * 20 + ks + t + 4]);
                af[mt][3] = f2tf32(as[(r + 8) * 20 + ks + t + 4]);
            }
            uint32_t bfr[4][2];
#pragma unroll
            for (int nt = 0; nt < 4; nt++) {
                const int c = wn + nt * 8 + g;
                bfr[nt][0] = f2tf32(bs[(ks + t) * 136 + c]);
                bfr[nt][1] = f2tf32(bs[(ks + t + 4) * 136 + c]);
            }
#pragma unroll
            for (int mt = 0; mt < 4; mt++)
#pragma unroll
                for (int nt = 0; nt < 4; nt++)
                    mma_tf32(acc[mt][nt], af[mt], bfr[nt]);
        }
    }

    // epilogue
#pragma unroll
    for (int mt = 0; mt < 4; mt++) {
        const int r = bm + wm + mt * 16 + g;
#pragma unroll
        for (int nt = 0; nt < 4; nt++) {
            const int c = bn + wn + nt * 8 + 2 * t;
            const float2 bb = *(const float2*)(bias + c);
            float2 v0, v1;
            v0.x = acc[mt][nt][0] + bb.x;  v0.y = acc[mt][nt][1] + bb.y;
            v1.x = acc[mt][nt][2] + bb.x;  v1.y = acc[mt][nt][3] + bb.y;
            if (EPI == 1) {
                v0.x = fmaxf(v0.x, 0.f); v0.y = fmaxf(v0.y, 0.f);
                v1.x = fmaxf(v1.x, 0.f); v1.y = fmaxf(v1.y, 0.f);
            }
            if (EPI == 2) {
                const float2 r0 = *(const float2*)(res + (size_t)r * N + c);
                const float2 r1 = *(const float2*)(res + (size_t)(r + 8) * N + c);
                v0.x += r0.x; v0.y += r0.y;
                v1.x += r1.x; v1.y += r1.y;
            }
            *(float2*)(C + (size_t)r * N + c)       = v0;
            *(float2*)(C + (size_t)(r + 8) * N + c) = v1;
        }
    }
}

// ---------------------------------------------------------------------------
// Tensor-core flash attention (tf32 mma) — unchanged from R3 (334us measured)
// ---------------------------------------------------------------------------
#define AQT 128
#define AKT 64
#define QP  68
#define KP  68
#define VP  72
#define PP  68
#define QS_OFF 0
#define KS_OFF (AQT * QP)
#define VS_OFF (KS_OFF + AKT * KP)
#define PS_OFF (VS_OFF + AKT * VP)
#define ATTN_SMEM_BYTES ((PS_OFF + AQT * PP) * 4)

__global__ __launch_bounds__(256, 2)
void attn_tc(const float* __restrict__ Q, const float* __restrict__ K,
             const float* __restrict__ V, float* __restrict__ O)
{
    extern __shared__ uint32_t sm_[];
    uint32_t* qs = sm_ + QS_OFF;
    uint32_t* ks = sm_ + KS_OFF;
    uint32_t* vs = sm_ + VS_OFF;
    uint32_t* ps = sm_ + PS_OFF;

    const int tid  = threadIdx.x;
    const int wid  = tid >> 5;
    const int lane = tid & 31;
    const int g    = lane >> 2;
    const int t    = lane & 3;
    const int bh   = blockIdx.y;
    const int b    = bh >> 4;
    const int h    = bh & 15;
    const int q0   = blockIdx.x * AQT;
    const size_t base = (size_t)b * SEQ * D_MODEL + (size_t)h * DK;

#pragma unroll
    for (int e = 0; e < 8; e++) {
        int idx = tid + 256 * e;
        int r = idx >> 4, c4 = (idx & 15) * 4;
        float4 qv = *(const float4*)(Q + base + (size_t)(q0 + r) * D_MODEL + c4);
        qs[r * QP + c4 + 0] = f2tf32(qv.x * 0.125f);
        qs[r * QP + c4 + 1] = f2tf32(qv.y * 0.125f);
        qs[r * QP + c4 + 2] = f2tf32(qv.z * 0.125f);
        qs[r * QP + c4 + 3] = f2tf32(qv.w * 0.125f);
    }

    float m0 = -1e30f, m1 = -1e30f, l0 = 0.f, l1 = 0.f;
    float oacc[8][4];
#pragma unroll
    for (int nt = 0; nt < 8; nt++)
#pragma unroll
        for (int e = 0; e < 4; e++) oacc[nt][e] = 0.f;

    const int qrow = wid * 16;

    for (int k0 = 0; k0 < SEQ; k0 += AKT) {
        __syncthreads();
#pragma unroll
        for (int e = 0; e < 4; e++) {
            int idx = tid + 256 * e;
            int r = idx >> 4, c4 = (idx & 15) * 4;
            float4 kv = *(const float4*)(K + base + (size_t)(k0 + r) * D_MODEL + c4);
            ks[r * KP + c4 + 0] = f2tf32(kv.x);
            ks[r * KP + c4 + 1] = f2tf32(kv.y);
            ks[r * KP + c4 + 2] = f2tf32(kv.z);
            ks[r * KP + c4 + 3] = f2tf32(kv.w);
            float4 vv = *(const float4*)(V + base + (size_t)(k0 + r) * D_MODEL + c4);
            vs[r * VP + c4 + 0] = f2tf32(vv.x);
            vs[r * VP + c4 + 1] = f2tf32(vv.y);
            vs[r * VP + c4 + 2] = f2tf32(vv.z);
            vs[r * VP + c4 + 3] = f2tf32(vv.w);
        }
        __syncthreads();

        float sacc[8][4];
#pragma unroll
        for (int nt = 0; nt < 8; nt++)
#pragma unroll
            for (int e = 0; e < 4; e++) sacc[nt][e] = 0.f;

#pragma unroll
        for (int k8 = 0; k8 < 8; k8++) {
            uint32_t a[4];
            a[0] = qs[(qrow + g    ) * QP + k8 * 8 + t];
            a[1] = qs[(qrow + g + 8) * QP + k8 * 8 + t];
            a[2] = qs[(qrow + g    ) * QP + k8 * 8 + t + 4];
            a[3] = qs[(qrow + g + 8) * QP + k8 * 8 + t + 4];
#pragma unroll
            for (int nt = 0; nt < 8; nt++) {
                uint32_t bb[2];
                bb[0] = ks[(nt * 8 + g) * KP + k8 * 8 + t];
                bb[1] = ks[(nt * 8 + g) * KP + k8 * 8 + t + 4];
                mma_tf32(sacc[nt], a, bb);
            }
        }

        float rmax0 = -1e30f, rmax1 = -1e30f;
#pragma unroll
        for (int nt = 0; nt < 8; nt++) {
            rmax0 = fmaxf(rmax0, fmaxf(sacc[nt][0], sacc[nt][1]));
            rmax1 = fmaxf(rmax1, fmaxf(sacc[nt][2], sacc[nt][3]));
        }
        rmax0 = fmaxf(rmax0, __shfl_xor_sync(0xffffffffu, rmax0, 1));
        rmax0 = fmaxf(rmax0, __shfl_xor_sync(0xffffffffu, rmax0, 2));
        rmax1 = fmaxf(rmax1, __shfl_xor_sync(0xffffffffu, rmax1, 1));
        rmax1 = fmaxf(rmax1, __shfl_xor_sync(0xffffffffu, rmax1, 2));

        const float nm0 = fmaxf(m0, rmax0);
        const float nm1 = fmaxf(m1, rmax1);
        const float sc0 = __expf(m0 - nm0);
        const float sc1 = __expf(m1 - nm1);

        float rs0 = 0.f, rs1 = 0.f;
#pragma unroll
        for (int nt = 0; nt < 8; nt++) {
            float p00 = __expf(sacc[nt][0] - nm0);
            float p01 = __expf(sacc[nt][1] - nm0);
            float p10 = __expf(sacc[nt][2] - nm1);
            float p11 = __expf(sacc[nt][3] - nm1);
            rs0 += p00 + p01;
            rs1 += p10 + p11;
            ps[(qrow + g    ) * PP + nt * 8 + 2 * t    ] = f2tf32(p00);
            ps[(qrow + g    ) * PP + nt * 8 + 2 * t + 1] = f2tf32(p01);
            ps[(qrow + g + 8) * PP + nt * 8 + 2 * t    ] = f2tf32(p10);
            ps[(qrow + g + 8) * PP + nt * 8 + 2 * t + 1] = f2tf32(p11);
        }
        rs0 += __shfl_xor_sync(0xffffffffu, rs0, 1);
        rs0 += __shfl_xor_sync(0xffffffffu, rs0, 2);
        rs1 += __shfl_xor_sync(0xffffffffu, rs1, 1);
        rs1 += __shfl_xor_sync(0xffffffffu, rs1, 2);

        m0 = nm0; m1 = nm1;
        l0 = l0 * sc0 + rs0;
        l1 = l1 * sc1 + rs1;
#pragma unroll
        for (int nt = 0; nt < 8; nt++) {
            oacc[nt][0] *= sc0; oacc[nt][1] *= sc0;
            oacc[nt][2] *= sc1; oacc[nt][3] *= sc1;
        }

        __syncwarp();

#pragma unroll
        for (int k8 = 0; k8 < 8; k8++) {
            uint32_t a[4];
            a[0] = ps[(qrow + g    ) * PP + k8 * 8 + t];
            a[1] = ps[(qrow + g + 8) * PP + k8 * 8 + t];
            a[2] = ps[(qrow + g    ) * PP + k8 * 8 + t + 4];
            a[3] = ps[(qrow + g + 8) * PP + k8 * 8 + t + 4];
#pragma unroll
            for (int nt = 0; nt < 8; nt++) {
                uint32_t bb[2];
                bb[0] = vs[(k8 * 8 + t    ) * VP + nt * 8 + g];
                bb[1] = vs[(k8 * 8 + t + 4) * VP + nt * 8 + g];
                mma_tf32(oacc[nt], a, bb);
            }
        }
    }

    const float il0 = 1.f / l0;
    const float il1 = 1.f / l1;
#pragma unroll
    for (int nt = 0; nt < 8; nt++) {
        const int c = nt * 8 + 2 * t;
        float2 v0, v1;
        v0.x = oacc[nt][0] * il0;  v0.y = oacc[nt][1] * il0;
        v1.x = oacc[nt][2] * il1;  v1.y = oacc[nt][3] * il1;
        *(float2*)(O + base + (size_t)(q0 + qrow + g    ) * D_MODEL + c) = v0;
        *(float2*)(O + base + (size_t)(q0 + qrow + g + 8) * D_MODEL + c) = v1;
    }
}

// ---------------------------------------------------------------------------
// LayerNorm over last dim (1024). One block (256 threads) per row.
// ---------------------------------------------------------------------------
__global__ __launch_bounds__(256)
void ln_kernel(const float* __restrict__ X, const float* __restrict__ g,
               const float* __restrict__ b, float* __restrict__ Y)
{
    const int row = blockIdx.x;
    const float* x = X + (size_t)row * D_MODEL;

    float v[4];
    float s = 0.f, s2 = 0.f;
#pragma unroll
    for (int e = 0; e < 4; e++) {
        v[e] = x[threadIdx.x + 256 * e];
        s  += v[e];
        s2 += v[e] * v[e];
    }
#pragma unroll
    for (int off = 16; off; off >>= 1) {
        s  += __shfl_xor_sync(0xffffffffu, s,  off);
        s2 += __shfl_xor_sync(0xffffffffu, s2, off);
    }
    __shared__ float rs[8], rs2[8];
    const int w = threadIdx.x >> 5, lane = threadIdx.x & 31;
    if (lane == 0) { rs[w] = s; rs2[w] = s2; }
    __syncthreads();
    s = 0.f; s2 = 0.f;
#pragma unroll
    for (int i = 0; i < 8; i++) { s += rs[i]; s2 += rs2[i]; }

    const float mean = s * (1.f / D_MODEL);
    const float var  = s2 * (1.f / D_MODEL) - mean * mean;
    const float rstd = rsqrtf(var + 1e-5f);

    float* y = Y + (size_t)row * D_MODEL;
#pragma unroll
    for (int e = 0; e < 4; e++) {
        int c = threadIdx.x + 256 * e;
        y[c] = (v[e] - mean) * rstd * g[c] + b[c];
    }
}

// ---------------------------------------------------------------------------
// Launch
// ---------------------------------------------------------------------------
extern "C" void kernel_launch(void* const* d_in, const int* in_sizes, int n_in,
                              void* d_out, int out_size)
{
    const float* x     = (const float*)d_in[0];
    const float* wq    = (const float*)d_in[1];
    const float* bq    = (const float*)d_in[2];
    const float* wk    = (const float*)d_in[3];
    const float* bk    = (const float*)d_in[4];
    const float* wv    = (const float*)d_in[5];
    const float* bv    = (const float*)d_in[6];
    const float* wo    = (const float*)d_in[7];
    const float* bo    = (const float*)d_in[8];
    const float* ln1_g = (const float*)d_in[9];
    const float* ln1_b = (const float*)d_in[10];
    const float* ln2_g = (const float*)d_in[11];
    const float* ln2_b = (const float*)d_in[12];
    const float* w1    = (const float*)d_in[13];
    const float* b1    = (const float*)d_in[14];
    const float* w2    = (const float*)d_in[15];
    const float* b2    = (const float*)d_in[16];
    float* out = (float*)d_out;

    float *q, *k, *v, *attn, *x1, *tmp, *hbuf;
    cudaGetSymbolAddress((void**)&q,    g_q);
    cudaGetSymbolAddress((void**)&k,    g_k);
    cudaGetSymbolAddress((void**)&v,    g_v);
    cudaGetSymbolAddress((void**)&attn, g_attn);
    cudaGetSymbolAddress((void**)&x1,   g_x1);
    cudaGetSymbolAddress((void**)&tmp,  g_tmp);
    cudaGetSymbolAddress((void**)&hbuf, g_h);

    cudaFuncSetAttribute(attn_tc, cudaFuncAttributeMaxDynamicSharedMemorySize,
                         ATTN_SMEM_BYTES);
    cudaFuncSetAttribute(gemm_tc<0>, cudaFuncAttributeMaxDynamicSharedMemorySize,
                         GEMM_SMEM_BYTES);
    cudaFuncSetAttribute(gemm_tc<1>, cudaFuncAttributeMaxDynamicSharedMemorySize,
                         GEMM_SMEM_BYTES);
    cudaFuncSetAttribute(gemm_tc<2>, cudaFuncAttributeMaxDynamicSharedMemorySize,
                         GEMM_SMEM_BYTES);

    const dim3 blk(256);
    const dim3 grid_d (D_MODEL / 128, MTOT / 128);
    const dim3 grid_ff(DFF / 128,     MTOT / 128);

    gemm_tc<0><<<grid_d, blk, GEMM_SMEM_BYTES>>>(x, wq, bq, nullptr, q, MTOT, D_MODEL, D_MODEL);
    gemm_tc<0><<<grid_d, blk, GEMM_SMEM_BYTES>>>(x, wk, bk, nullptr, k, MTOT, D_MODEL, D_MODEL);
    gemm_tc<0><<<grid_d, blk, GEMM_SMEM_BYTES>>>(x, wv, bv, nullptr, v, MTOT, D_MODEL, D_MODEL);

    attn_tc<<<dim3(SEQ / AQT, BATCH * NH), blk, ATTN_SMEM_BYTES>>>(q, k, v, attn);

    gemm_tc<2><<<grid_d, blk, GEMM_SMEM_BYTES>>>(attn, wo, bo, x, tmp, MTOT, D_MODEL, D_MODEL);
    ln_kernel<<<MTOT, blk>>>(tmp, ln1_g, ln1_b, x1);

    gemm_tc<1><<<grid_ff, blk, GEMM_SMEM_BYTES>>>(x1, w1, b1, nullptr, hbuf, MTOT, DFF, D_MODEL);
    gemm_tc<2><<<grid_d, blk, GEMM_SMEM_BYTES>>>(hbuf, w2, b2, x1, tmp, MTOT, D_MODEL, DFF);
    ln_kernel<<<MTOT, blk>>>(tmp, ln2_g, ln2_b, out);
}

// round 5
// speedup vs baseline: 4.5444x; 1.1627x over previous
#include <cuda_runtime.h>
#include <cstdint>
#include <cstddef>

// Problem dims (fixed by the reference)
#define D_MODEL 1024
#define SEQ     2048
#define BATCH   2
#define NH      16
#define DK      64
#define DFF     4096
#define MTOT    (BATCH * SEQ)   // 4096 rows

// ---------------------------------------------------------------------------
// Scratch (no allocation allowed -> __device__ globals)
// ---------------------------------------------------------------------------
__device__ float    g_qkv  [3 * MTOT * D_MODEL];   // q | k | v
__device__ uint32_t g_attnT[MTOT * D_MODEL];       // attn out, tf32
__device__ float    g_x1   [MTOT * D_MODEL];
__device__ uint32_t g_x1T  [MTOT * D_MODEL];
__device__ float    g_tmp  [MTOT * D_MODEL];
__device__ uint32_t g_hT   [MTOT * DFF];           // relu(ffn1), tf32
__device__ uint32_t g_xT   [MTOT * D_MODEL];       // x, tf32
__device__ uint32_t g_wqkvT[3 * D_MODEL * D_MODEL];
__device__ uint32_t g_woT  [D_MODEL * D_MODEL];
__device__ uint32_t g_w1T  [D_MODEL * DFF];
__device__ uint32_t g_w2T  [D_MODEL * DFF];

// ---------------------------------------------------------------------------
// helpers
// ---------------------------------------------------------------------------
__device__ __forceinline__ uint32_t f2tf32(float x) {
    uint32_t u;
    asm("cvt.rna.tf32.f32 %0, %1;" : "=r"(u) : "f"(x));
    return u;
}

__device__ __forceinline__ void mma_tf32(float c[4], const uint32_t a[4],
                                         const uint32_t b[2]) {
    asm("mma.sync.aligned.m16n8k8.row.col.f32.tf32.tf32.f32 "
        "{%0,%1,%2,%3}, {%4,%5,%6,%7}, {%8,%9}, {%0,%1,%2,%3};"
        : "+f"(c[0]), "+f"(c[1]), "+f"(c[2]), "+f"(c[3])
        : "r"(a[0]), "r"(a[1]), "r"(a[2]), "r"(a[3]), "r"(b[0]), "r"(b[1]));
}

__device__ __forceinline__ void ldm_x4(uint32_t r[4], uint32_t addr) {
    asm volatile("ldmatrix.sync.aligned.m8n8.x4.shared.b16 {%0,%1,%2,%3}, [%4];"
                 : "=r"(r[0]), "=r"(r[1]), "=r"(r[2]), "=r"(r[3]) : "r"(addr));
}

__device__ __forceinline__ void cp16(uint32_t saddr, const void* gptr) {
    asm volatile("cp.async.cg.shared.global [%0], [%1], 16;"
                 :: "r"(saddr), "l"(gptr));
}
__device__ __forceinline__ void cp_commit() { asm volatile("cp.async.commit_group;"); }
__device__ __forceinline__ void cp_wait2()  { asm volatile("cp.async.wait_group 2;"); }

// ---------------------------------------------------------------------------
// Tensor-core GEMM core. All operands pre-converted tf32.
// A: [M][K] tf32 row-major. WT: [N][K] tf32 (weights pre-transposed).
// Block tile 128x128 x K16, 8 warps (2M x 4N), warp tile 64x32, m16n8k8.
// Smem: A and B tiles both 128 rows x 16 k-words, pitch 20 words
// (ldmatrix row phase banks (5r)%8 all distinct -> conflict-free).
// Fragments via ldmatrix.x4. cp.async 4-stage pipeline.
// EPI: 0 = bias, 1 = bias+relu, 2 = bias+res. TFOUT: store tf32 bits.
// ---------------------------------------------------------------------------
#define GP 20
#define ASTG (128 * GP)             // words per A tile = 2560
#define STGW (2 * ASTG)             // A+B per stage = 5120 words
#define GSTAGES 4
#define GEMM_SMEM_BYTES (GSTAGES * STGW * 4)   // 81920

template <int EPI, bool TFOUT>
__device__ __forceinline__ void gemm_body(
    const uint32_t* __restrict__ A, const uint32_t* __restrict__ WT,
    const float* __restrict__ bias, const float* __restrict__ res,
    void* __restrict__ Cv, int M, int N, int K, int bm, int bn)
{
    extern __shared__ uint32_t gsm[];

    const int tid  = threadIdx.x;
    const int wid  = tid >> 5;
    const int lane = tid & 31;
    const int g    = lane >> 2;
    const int t    = lane & 3;
    const int wm   = (wid & 1) * 64;
    const int wn   = (wid >> 1) * 32;

    float acc[4][4][4];
#pragma unroll
    for (int i = 0; i < 4; i++)
#pragma unroll
        for (int j = 0; j < 4; j++)
#pragma unroll
            for (int e = 0; e < 4; e++) acc[i][j][e] = 0.f;

    // cp.async: 128 rows x 4 16B-chunks per tile; thread -> (row, chunk), x2 rows
    const int cr = tid >> 2, cc = (tid & 3) * 4;
    const uint32_t sbase = (uint32_t)__cvta_generic_to_shared(gsm);
    const uint32_t aS = sbase + (cr * GP + cc) * 4;
    const uint32_t bS = aS + ASTG * 4;
    const uint32_t* aG0 = A  + (size_t)(bm + cr) * K + cc;
    const uint32_t* aG1 = aG0 + (size_t)64 * K;
    const uint32_t* bG0 = WT + (size_t)(bn + cr) * K + cc;
    const uint32_t* bG1 = bG0 + (size_t)64 * K;

#define GI(kt)                                                                 \
    {                                                                          \
        const uint32_t so_ = ((kt) & 3) * (STGW * 4);                          \
        const int k0_ = (kt) * 16;                                             \
        cp16(aS + so_, aG0 + k0_);                                             \
        cp16(aS + so_ + 64 * GP * 4, aG1 + k0_);                               \
        cp16(bS + so_, bG0 + k0_);                                             \
        cp16(bS + so_ + 64 * GP * 4, bG1 + k0_);                               \
    }

    // ldmatrix per-lane row addresses
    const int lrow = lane & 7, lsel = lane >> 3;
    const int a_ro = (lsel & 1) * 8 + lrow;     // matrix order: r0=a0,r1=a1,r2=a2,r3=a3
    const int a_co = (lsel >> 1) * 4;
    uint32_t a_lm[4];
#pragma unroll
    for (int mt = 0; mt < 4; mt++)
        a_lm[mt] = sbase + ((wm + mt * 16 + a_ro) * GP + a_co) * 4;
    const int b_ro = (lsel >> 1) * 8 + lrow;    // m0/m1 = nt-even b0/b1, m2/m3 = nt-odd
    const int b_co = (lsel & 1) * 4;
    uint32_t b_lm[2];
#pragma unroll
    for (int p = 0; p < 2; p++)
        b_lm[p] = sbase + ASTG * 4 + ((wn + p * 16 + b_ro) * GP + b_co) * 4;

    const int nk = K >> 4;
#pragma unroll
    for (int s = 0; s < GSTAGES - 1; s++) { GI(s) cp_commit(); }

    for (int kt = 0; kt < nk; kt++) {
        cp_wait2();
        __syncthreads();
        if (kt + GSTAGES - 1 < nk) { GI(kt + GSTAGES - 1) }
        cp_commit();

        const uint32_t so = (kt & 3) * (STGW * 4);
#pragma unroll
        for (int ks = 0; ks < 16; ks += 8) {
            uint32_t af[4][4];
#pragma unroll
            for (int mt = 0; mt < 4; mt++)
                ldm_x4(af[mt], a_lm[mt] + so + ks * 4);
            uint32_t bf[2][4];
            ldm_x4(bf[0], b_lm[0] + so + ks * 4);
            ldm_x4(bf[1], b_lm[1] + so + ks * 4);
#pragma unroll
            for (int mt = 0; mt < 4; mt++)
#pragma unroll
                for (int nt = 0; nt < 4; nt++)
                    mma_tf32(acc[mt][nt], af[mt], &bf[nt >> 1][(nt & 1) * 2]);
        }
    }
#undef GI

    // epilogue
#pragma unroll
    for (int mt = 0; mt < 4; mt++) {
        const int r = bm + wm + mt * 16 + g;
#pragma unroll
        for (int nt = 0; nt < 4; nt++) {
            const int c = bn + wn + nt * 8 + 2 * t;
            const float2 bb = *(const float2*)(bias + c);
            float2 v0, v1;
            v0.x = acc[mt][nt][0] + bb.x;  v0.y = acc[mt][nt][1] + bb.y;
            v1.x = acc[mt][nt][2] + bb.x;  v1.y = acc[mt][nt][3] + bb.y;
            if (EPI == 1) {
                v0.x = fmaxf(v0.x, 0.f); v0.y = fmaxf(v0.y, 0.f);
                v1.x = fmaxf(v1.x, 0.f); v1.y = fmaxf(v1.y, 0.f);
            }
            if (EPI == 2) {
                const float2 r0 = *(const float2*)(res + (size_t)r * N + c);
                const float2 r1 = *(const float2*)(res + (size_t)(r + 8) * N + c);
                v0.x += r0.x; v0.y += r0.y;
                v1.x += r1.x; v1.y += r1.y;
            }
            if (TFOUT) {
                uint32_t* C = (uint32_t*)Cv;
                uint2 u0 = make_uint2(f2tf32(v0.x), f2tf32(v0.y));
                uint2 u1 = make_uint2(f2tf32(v1.x), f2tf32(v1.y));
                *(uint2*)(C + (size_t)r * N + c)       = u0;
                *(uint2*)(C + (size_t)(r + 8) * N + c) = u1;
            } else {
                float* C = (float*)Cv;
                *(float2*)(C + (size_t)r * N + c)       = v0;
                *(float2*)(C + (size_t)(r + 8) * N + c) = v1;
            }
        }
    }
}

template <int EPI, bool TFOUT>
__global__ __launch_bounds__(256, 2)
void gemm_tc(const uint32_t* __restrict__ A, const uint32_t* __restrict__ WT,
             const float* __restrict__ bias, const float* __restrict__ res,
             void* __restrict__ C, int M, int N, int K)
{
    gemm_body<EPI, TFOUT>(A, WT, bias, res, C, M, N, K,
                          blockIdx.y * 128, blockIdx.x * 128);
}

// fused QKV: gridDim.z = 3 selects weight slab / bias / output slab
__global__ __launch_bounds__(256, 2)
void qkv_tc(const uint32_t* __restrict__ xT, const uint32_t* __restrict__ wqkvT,
            const float* __restrict__ bq, const float* __restrict__ bk,
            const float* __restrict__ bv, float* __restrict__ qkv)
{
    const int z = blockIdx.z;
    const float* bias = (z == 0) ? bq : (z == 1) ? bk : bv;
    gemm_body<0, false>(xT, wqkvT + (size_t)z * D_MODEL * D_MODEL, bias, nullptr,
                        qkv + (size_t)z * MTOT * D_MODEL,
                        MTOT, D_MODEL, D_MODEL, blockIdx.y * 128, blockIdx.x * 128);
}

// ---------------------------------------------------------------------------
// Pre-pass: transpose + tf32-convert weights; convert x.
// ---------------------------------------------------------------------------
__device__ __forceinline__ void transp_body(const float* __restrict__ W,
                                            uint32_t* __restrict__ WT, int K, int N)
{
    __shared__ float tl[32][33];
    const int n0 = blockIdx.x * 32, k0 = blockIdx.y * 32;
    const int tx = threadIdx.x, ty = threadIdx.y;
#pragma unroll
    for (int i = 0; i < 32; i += 8)
        tl[ty + i][tx] = W[(size_t)(k0 + ty + i) * N + n0 + tx];
    __syncthreads();
#pragma unroll
    for (int i = 0; i < 32; i += 8)
        WT[(size_t)(n0 + ty + i) * K + k0 + tx] = f2tf32(tl[tx][ty + i]);
}

__global__ void transp_qkvo(const float* __restrict__ wq, const float* __restrict__ wk,
                            const float* __restrict__ wv, const float* __restrict__ wo,
                            uint32_t* __restrict__ qkvT, uint32_t* __restrict__ woT)
{
    const int z = blockIdx.z;
    const float* W = (z == 0) ? wq : (z == 1) ? wk : (z == 2) ? wv : wo;
    uint32_t* WT = (z < 3) ? qkvT + (size_t)z * D_MODEL * D_MODEL : woT;
    transp_body(W, WT, D_MODEL, D_MODEL);
}

__global__ void transp_gen(const float* __restrict__ W, uint32_t* __restrict__ WT,
                           int K, int N)
{
    transp_body(W, WT, K, N);
}

__global__ void cvt_tf32_vec(const float* __restrict__ X, uint32_t* __restrict__ Y)
{
    const int i = blockIdx.x * blockDim.x + threadIdx.x;
    float4 v = ((const float4*)X)[i];
    uint4 u;
    u.x = f2tf32(v.x); u.y = f2tf32(v.y); u.z = f2tf32(v.z); u.w = f2tf32(v.w);
    ((uint4*)Y)[i] = u;
}

// ---------------------------------------------------------------------------
// Tensor-core flash attention (tf32 mma) — unchanged from R3 except the
// epilogue writes tf32 bits (feeds the O-projection GEMM directly).
// ---------------------------------------------------------------------------
#define AQT 128
#define AKT 64
#define QP  68
#define KP  68
#define VP  72
#define PP  68
#define QS_OFF 0
#define KS_OFF (AQT * QP)
#define VS_OFF (KS_OFF + AKT * KP)
#define PS_OFF (VS_OFF + AKT * VP)
#define ATTN_SMEM_BYTES ((PS_OFF + AQT * PP) * 4)

__global__ __launch_bounds__(256, 2)
void attn_tc(const float* __restrict__ Q, const float* __restrict__ K,
             const float* __restrict__ V, uint32_t* __restrict__ O)
{
    extern __shared__ uint32_t asmem[];
    uint32_t* qs = asmem + QS_OFF;
    uint32_t* ks = asmem + KS_OFF;
    uint32_t* vs = asmem + VS_OFF;
    uint32_t* ps = asmem + PS_OFF;

    const int tid  = threadIdx.x;
    const int wid  = tid >> 5;
    const int lane = tid & 31;
    const int g    = lane >> 2;
    const int t    = lane & 3;
    const int bh   = blockIdx.y;
    const int b    = bh >> 4;
    const int h    = bh & 15;
    const int q0   = blockIdx.x * AQT;
    const size_t base = (size_t)b * SEQ * D_MODEL + (size_t)h * DK;

#pragma unroll
    for (int e = 0; e < 8; e++) {
        int idx = tid + 256 * e;
        int r = idx >> 4, c4 = (idx & 15) * 4;
        float4 qv = *(const float4*)(Q + base + (size_t)(q0 + r) * D_MODEL + c4);
        qs[r * QP + c4 + 0] = f2tf32(qv.x * 0.125f);
        qs[r * QP + c4 + 1] = f2tf32(qv.y * 0.125f);
        qs[r * QP + c4 + 2] = f2tf32(qv.z * 0.125f);
        qs[r * QP + c4 + 3] = f2tf32(qv.w * 0.125f);
    }

    float m0 = -1e30f, m1 = -1e30f, l0 = 0.f, l1 = 0.f;
    float oacc[8][4];
#pragma unroll
    for (int nt = 0; nt < 8; nt++)
#pragma unroll
        for (int e = 0; e < 4; e++) oacc[nt][e] = 0.f;

    const int qrow = wid * 16;

    for (int k0 = 0; k0 < SEQ; k0 += AKT) {
        __syncthreads();
#pragma unroll
        for (int e = 0; e < 4; e++) {
            int idx = tid + 256 * e;
            int r = idx >> 4, c4 = (idx & 15) * 4;
            float4 kv = *(const float4*)(K + base + (size_t)(k0 + r) * D_MODEL + c4);
            ks[r * KP + c4 + 0] = f2tf32(kv.x);
            ks[r * KP + c4 + 1] = f2tf32(kv.y);
            ks[r * KP + c4 + 2] = f2tf32(kv.z);
            ks[r * KP + c4 + 3] = f2tf32(kv.w);
            float4 vv = *(const float4*)(V + base + (size_t)(k0 + r) * D_MODEL + c4);
            vs[r * VP + c4 + 0] = f2tf32(vv.x);
            vs[r * VP + c4 + 1] = f2tf32(vv.y);
            vs[r * VP + c4 + 2] = f2tf32(vv.z);
            vs[r * VP + c4 + 3] = f2tf32(vv.w);
        }
        __syncthreads();

        float sacc[8][4];
#pragma unroll
        for (int nt = 0; nt < 8; nt++)
#pragma unroll
            for (int e = 0; e < 4; e++) sacc[nt][e] = 0.f;

#pragma unroll
        for (int k8 = 0; k8 < 8; k8++) {
            uint32_t a[4];
            a[0] = qs[(qrow + g    ) * QP + k8 * 8 + t];
            a[1] = qs[(qrow + g + 8) * QP + k8 * 8 + t];
            a[2] = qs[(qrow + g    ) * QP + k8 * 8 + t + 4];
            a[3] = qs[(qrow + g + 8) * QP + k8 * 8 + t + 4];
#pragma unroll
            for (int nt = 0; nt < 8; nt++) {
                uint32_t bb[2];
                bb[0] = ks[(nt * 8 + g) * KP + k8 * 8 + t];
                bb[1] = ks[(nt * 8 + g) * KP + k8 * 8 + t + 4];
                mma_tf32(sacc[nt], a, bb);
            }
        }

        float rmax0 = -1e30f, rmax1 = -1e30f;
#pragma unroll
        for (int nt = 0; nt < 8; nt++) {
            rmax0 = fmaxf(rmax0, fmaxf(sacc[nt][0], sacc[nt][1]));
            rmax1 = fmaxf(rmax1, fmaxf(sacc[nt][2], sacc[nt][3]));
        }
        rmax0 = fmaxf(rmax0, __shfl_xor_sync(0xffffffffu, rmax0, 1));
        rmax0 = fmaxf(rmax0, __shfl_xor_sync(0xffffffffu, rmax0, 2));
        rmax1 = fmaxf(rmax1, __shfl_xor_sync(0xffffffffu, rmax1, 1));
        rmax1 = fmaxf(rmax1, __shfl_xor_sync(0xffffffffu, rmax1, 2));

        const float nm0 = fmaxf(m0, rmax0);
        const float nm1 = fmaxf(m1, rmax1);
        const float sc0 = __expf(m0 - nm0);
        const float sc1 = __expf(m1 - nm1);

        float rs0 = 0.f, rs1 = 0.f;
#pragma unroll
        for (int nt = 0; nt < 8; nt++) {
            float p00 = __expf(sacc[nt][0] - nm0);
            float p01 = __expf(sacc[nt][1] - nm0);
            float p10 = __expf(sacc[nt][2] - nm1);
            float p11 = __expf(sacc[nt][3] - nm1);
            rs0 += p00 + p01;
            rs1 += p10 + p11;
            ps[(qrow + g    ) * PP + nt * 8 + 2 * t    ] = f2tf32(p00);
            ps[(qrow + g    ) * PP + nt * 8 + 2 * t + 1] = f2tf32(p01);
            ps[(qrow + g + 8) * PP + nt * 8 + 2 * t    ] = f2tf32(p10);
            ps[(qrow + g + 8) * PP + nt * 8 + 2 * t + 1] = f2tf32(p11);
        }
        rs0 += __shfl_xor_sync(0xffffffffu, rs0, 1);
        rs0 += __shfl_xor_sync(0xffffffffu, rs0, 2);
        rs1 += __shfl_xor_sync(0xffffffffu, rs1, 1);
        rs1 += __shfl_xor_sync(0xffffffffu, rs1, 2);

        m0 = nm0; m1 = nm1;
        l0 = l0 * sc0 + rs0;
        l1 = l1 * sc1 + rs1;
#pragma unroll
        for (int nt = 0; nt < 8; nt++) {
            oacc[nt][0] *= sc0; oacc[nt][1] *= sc0;
            oacc[nt][2] *= sc1; oacc[nt][3] *= sc1;
        }

        __syncwarp();

#pragma unroll
        for (int k8 = 0; k8 < 8; k8++) {
            uint32_t a[4];
            a[0] = ps[(qrow + g    ) * PP + k8 * 8 + t];
            a[1] = ps[(qrow + g + 8) * PP + k8 * 8 + t];
            a[2] = ps[(qrow + g    ) * PP + k8 * 8 + t + 4];
            a[3] = ps[(qrow + g + 8) * PP + k8 * 8 + t + 4];
#pragma unroll
            for (int nt = 0; nt < 8; nt++) {
                uint32_t bb[2];
                bb[0] = vs[(k8 * 8 + t    ) * VP + nt * 8 + g];
                bb[1] = vs[(k8 * 8 + t + 4) * VP + nt * 8 + g];
                mma_tf32(oacc[nt], a, bb);
            }
        }
    }

    const float il0 = 1.f / l0;
    const float il1 = 1.f / l1;
#pragma unroll
    for (int nt = 0; nt < 8; nt++) {
        const int c = nt * 8 + 2 * t;
        uint2 u0, u1;
        u0.x = f2tf32(oacc[nt][0] * il0);  u0.y = f2tf32(oacc[nt][1] * il0);
        u1.x = f2tf32(oacc[nt][2] * il1);  u1.y = f2tf32(oacc[nt][3] * il1);
        *(uint2*)(O + base + (size_t)(q0 + qrow + g    ) * D_MODEL + c) = u0;
        *(uint2*)(O + base + (size_t)(q0 + qrow + g + 8) * D_MODEL + c) = u1;
    }
}

// ---------------------------------------------------------------------------
// LayerNorm over last dim (1024); optional tf32 copy output.
// ---------------------------------------------------------------------------
__global__ __launch_bounds__(256)
void ln_kernel(const float* __restrict__ X, const float* __restrict__ g,
               const float* __restrict__ b, float* __restrict__ Y,
               uint32_t* __restrict__ Ytf)
{
    const int row = blockIdx.x;
    const float* x = X + (size_t)row * D_MODEL;

    float v[4];
    float s = 0.f, s2 = 0.f;
#pragma unroll
    for (int e = 0; e < 4; e++) {
        v[e] = x[threadIdx.x + 256 * e];
        s  += v[e];
        s2 += v[e] * v[e];
    }
#pragma unroll
    for (int off = 16; off; off >>= 1) {
        s  += __shfl_xor_sync(0xffffffffu, s,  off);
        s2 += __shfl_xor_sync(0xffffffffu, s2, off);
    }
    __shared__ float rs[8], rs2[8];
    const int w = threadIdx.x >> 5, lane = threadIdx.x & 31;
    if (lane == 0) { rs[w] = s; rs2[w] = s2; }
    __syncthreads();
    s = 0.f; s2 = 0.f;
#pragma unroll
    for (int i = 0; i < 8; i++) { s += rs[i]; s2 += rs2[i]; }

    const float mean = s * (1.f / D_MODEL);
    const float var  = s2 * (1.f / D_MODEL) - mean * mean;
    const float rstd = rsqrtf(var + 1e-5f);

    float* y = Y + (size_t)row * D_MODEL;
#pragma unroll
    for (int e = 0; e < 4; e++) {
        int c = threadIdx.x + 256 * e;
        float val = (v[e] - mean) * rstd * g[c] + b[c];
        y[c] = val;
        if (Ytf) Ytf[(size_t)row * D_MODEL + c] = f2tf32(val);
    }
}

// ---------------------------------------------------------------------------
// Launch
// ---------------------------------------------------------------------------
extern "C" void kernel_launch(void* const* d_in, const int* in_sizes, int n_in,
                              void* d_out, int out_size)
{
    const float* x     = (const float*)d_in[0];
    const float* wq    = (const float*)d_in[1];
    const float* bq    = (const float*)d_in[2];
    const float* wk    = (const float*)d_in[3];
    const float* bk    = (const float*)d_in[4];
    const float* wv    = (const float*)d_in[5];
    const float* bv    = (const float*)d_in[6];
    const float* wo    = (const float*)d_in[7];
    const float* bo    = (const float*)d_in[8];
    const float* ln1_g = (const float*)d_in[9];
    const float* ln1_b = (const float*)d_in[10];
    const float* ln2_g = (const float*)d_in[11];
    const float* ln2_b = (const float*)d_in[12];
    const float* w1    = (const float*)d_in[13];
    const float* b1    = (const float*)d_in[14];
    const float* w2    = (const float*)d_in[15];
    const float* b2    = (const float*)d_in[16];
    float* out = (float*)d_out;

    float *qkv, *x1, *tmp;
    uint32_t *attnT, *x1T, *hT, *xT, *wqkvT, *woT, *w1T, *w2T;
    cudaGetSymbolAddress((void**)&qkv,   g_qkv);
    cudaGetSymbolAddress((void**)&attnT, g_attnT);
    cudaGetSymbolAddress((void**)&x1,    g_x1);
    cudaGetSymbolAddress((void**)&x1T,   g_x1T);
    cudaGetSymbolAddress((void**)&tmp,   g_tmp);
    cudaGetSymbolAddress((void**)&hT,    g_hT);
    cudaGetSymbolAddress((void**)&xT,    g_xT);
    cudaGetSymbolAddress((void**)&wqkvT, g_wqkvT);
    cudaGetSymbolAddress((void**)&woT,   g_woT);
    cudaGetSymbolAddress((void**)&w1T,   g_w1T);
    cudaGetSymbolAddress((void**)&w2T,   g_w2T);

    cudaFuncSetAttribute(attn_tc, cudaFuncAttributeMaxDynamicSharedMemorySize,
                         ATTN_SMEM_BYTES);
    cudaFuncSetAttribute(qkv_tc, cudaFuncAttributeMaxDynamicSharedMemorySize,
                         GEMM_SMEM_BYTES);
    cudaFuncSetAttribute(gemm_tc<2, false>, cudaFuncAttributeMaxDynamicSharedMemorySize,
                         GEMM_SMEM_BYTES);
    cudaFuncSetAttribute(gemm_tc<1, true>, cudaFuncAttributeMaxDynamicSharedMemorySize,
                         GEMM_SMEM_BYTES);

    const dim3 blk(256);
    const dim3 tblk(32, 8);

    // pre-pass: convert x; transpose+convert weights
    cvt_tf32_vec<<<MTOT * D_MODEL / 4 / 256, blk>>>(x, xT);
    transp_qkvo<<<dim3(32, 32, 4), tblk>>>(wq, wk, wv, wo, wqkvT, woT);
    transp_gen<<<dim3(DFF / 32, D_MODEL / 32), tblk>>>(w1, w1T, D_MODEL, DFF);
    transp_gen<<<dim3(D_MODEL / 32, DFF / 32), tblk>>>(w2, w2T, DFF, D_MODEL);

    // QKV (fused, z = 0/1/2)
    qkv_tc<<<dim3(D_MODEL / 128, MTOT / 128, 3), blk, GEMM_SMEM_BYTES>>>(
        xT, wqkvT, bq, bk, bv, qkv);

    // attention
    attn_tc<<<dim3(SEQ / AQT, BATCH * NH), blk, ATTN_SMEM_BYTES>>>(
        qkv, qkv + (size_t)MTOT * D_MODEL, qkv + (size_t)2 * MTOT * D_MODEL, attnT);

    // O-proj + residual -> LN1
    gemm_tc<2, false><<<dim3(D_MODEL / 128, MTOT / 128), blk, GEMM_SMEM_BYTES>>>(
        attnT, woT, bo, x, tmp, MTOT, D_MODEL, D_MODEL);
    ln_kernel<<<MTOT, blk>>>(tmp, ln1_g, ln1_b, x1, x1T);

    // FFN
    gemm_tc<1, true><<<dim3(DFF / 128, MTOT / 128), blk, GEMM_SMEM_BYTES>>>(
        x1T, w1T, b1, nullptr, hT, MTOT, DFF, D_MODEL);
    gemm_tc<2, false><<<dim3(D_MODEL / 128, MTOT / 128), blk, GEMM_SMEM_BYTES>>>(
        hT, w2T, b2, x1, tmp, MTOT, D_MODEL, DFF);
    ln_kernel<<<MTOT, blk>>>(tmp, ln2_g, ln2_b, out, nullptr);
}